// round 1
// baseline (speedup 1.0000x reference)
#include <cuda_runtime.h>
#include <math.h>

#define BATCH 8
#define SEQ   2048
#define DIM   512
#define M_TOT (BATCH * SEQ)   // 16384

// Scratch (device globals: allocation-free per harness rules)
__device__ float g_sig[M_TOT * DIM];   // sigmoid(q)
__device__ float g_kw [M_TOT * DIM];   // exp(k)
__device__ float g_kwv[M_TOT * DIM];   // exp(k) * v
__device__ float g_wt [3 * DIM * DIM]; // Wq^T, Wk^T, Wv^T  (Wt[k][n] = W[n][k])

// ---------------------------------------------------------------------------
// Transpose the three weight matrices: Wt[k][n] = W[n][k]
// grid (DIM/32, DIM/32, 3), block (32, 8)
// ---------------------------------------------------------------------------
__global__ void transpose_w_kernel(const float* __restrict__ Wq,
                                   const float* __restrict__ Wk,
                                   const float* __restrict__ Wv) {
    __shared__ float tile[32][33];
    const float* W = (blockIdx.z == 0) ? Wq : (blockIdx.z == 1) ? Wk : Wv;
    float* Wt = g_wt + blockIdx.z * DIM * DIM;

    int x = blockIdx.x * 32 + threadIdx.x;   // col of W (k index)
    int y = blockIdx.y * 32 + threadIdx.y;   // row of W (n index)
    #pragma unroll
    for (int j = 0; j < 32; j += 8)
        tile[threadIdx.y + j][threadIdx.x] = W[(y + j) * DIM + x];
    __syncthreads();
    int xo = blockIdx.y * 32 + threadIdx.x;  // n
    int yo = blockIdx.x * 32 + threadIdx.y;  // k
    #pragma unroll
    for (int j = 0; j < 32; j += 8)
        Wt[(yo + j) * DIM + xo] = tile[threadIdx.x][threadIdx.y + j];
}

// ---------------------------------------------------------------------------
// QKV GEMM: C[m,n] = sum_k A[m,k] * Wt[k,n],  M=16384, N=512, K=512
// BM=64, BN=64, BK=16, 256 threads, 4x4 per thread.
// EPI 0: sigmoid(acc)   -> g_sig
// EPI 1: exp(acc)       -> g_kw
// EPI 2: exp_k * acc    -> g_kwv   (aux = g_kw, already computed)
// grid (DIM/64, M_TOT/64)
// ---------------------------------------------------------------------------
template <int EPI>
__global__ void __launch_bounds__(256)
gemm_qkv_kernel(const float* __restrict__ A,
                const float* __restrict__ Wt,
                float* __restrict__ C,
                const float* __restrict__ aux) {
    __shared__ float As[64][16];     // [m][k]
    __shared__ float Bs[16][64];     // [k][n]

    const int t  = threadIdx.x;
    const int tx = t & 15;           // n sub-tile
    const int ty = t >> 4;           // m sub-tile
    const int m0 = blockIdx.y * 64;
    const int n0 = blockIdx.x * 64;

    float acc[4][4] = {};

    for (int k0 = 0; k0 < DIM; k0 += 16) {
        // load A tile: 64x16, one float4 per thread
        {
            int r = t >> 2, c = (t & 3) << 2;
            float4 v = *(const float4*)&A[(m0 + r) * DIM + k0 + c];
            *(float4*)&As[r][c] = v;
        }
        // load Wt tile: 16x64, one float4 per thread
        {
            int r = t >> 4, c = (t & 15) << 2;
            float4 v = *(const float4*)&Wt[(k0 + r) * DIM + n0 + c];
            *(float4*)&Bs[r][c] = v;
        }
        __syncthreads();

        #pragma unroll
        for (int kk = 0; kk < 16; kk++) {
            float a[4], b[4];
            #pragma unroll
            for (int i = 0; i < 4; i++) a[i] = As[ty * 4 + i][kk];
            float4 bf = *(float4*)&Bs[kk][tx * 4];
            b[0] = bf.x; b[1] = bf.y; b[2] = bf.z; b[3] = bf.w;
            #pragma unroll
            for (int i = 0; i < 4; i++)
                #pragma unroll
                for (int j = 0; j < 4; j++)
                    acc[i][j] = fmaf(a[i], b[j], acc[i][j]);
        }
        __syncthreads();
    }

    #pragma unroll
    for (int i = 0; i < 4; i++) {
        int row = m0 + ty * 4 + i;
        int idx = row * DIM + n0 + tx * 4;
        float4 o;
        float v[4];
        #pragma unroll
        for (int j = 0; j < 4; j++) v[j] = acc[i][j];
        if (EPI == 0) {
            #pragma unroll
            for (int j = 0; j < 4; j++) v[j] = 1.0f / (1.0f + __expf(-v[j]));
        } else if (EPI == 1) {
            #pragma unroll
            for (int j = 0; j < 4; j++) v[j] = __expf(v[j]);
        } else {
            float4 kw = *(const float4*)&aux[idx];
            v[0] *= kw.x; v[1] *= kw.y; v[2] *= kw.z; v[3] *= kw.w;
        }
        o.x = v[0]; o.y = v[1]; o.z = v[2]; o.w = v[3];
        *(float4*)&C[idx] = o;
    }
}

// ---------------------------------------------------------------------------
// Main attention kernel: for each batch b,
//   out[b,j,d] = sig[b,j,d] * (sum_i dw[b,i,j]*kwv[b,i,d]) / (sum_i dw[b,i,j]*kw[b,i,d])
// with dw = exp(-alpha*log2(N)*dis[b,i,j]) computed on the fly.
// BM=64 (j), BN=64 (d), BK=32 (i), 256 threads, dual 4x4 accumulators.
// grid (DIM/64, SEQ/64, BATCH)
// ---------------------------------------------------------------------------
__global__ void __launch_bounds__(256)
attn_kernel(const float* __restrict__ dis,
            const float* __restrict__ alpha_p,
            float* __restrict__ out) {
    __shared__ float dw_s[32][64];   // [i][j]
    __shared__ float x1_s[32][64];   // [i][d] kwv
    __shared__ float x2_s[32][64];   // [i][d] kw

    const int t  = threadIdx.x;
    const int tx = t & 15;           // d sub-tile
    const int ty = t >> 4;           // j sub-tile
    const int b  = blockIdx.z;
    const int j0 = blockIdx.y * 64;
    const int d0 = blockIdx.x * 64;

    const float coef = -(alpha_p[0] * 11.0f);   // -alpha*log2(2048)

    const float* disb = dis + (size_t)b * SEQ * SEQ;
    const float* kwvb = g_kwv + (size_t)b * SEQ * DIM;
    const float* kwb  = g_kw  + (size_t)b * SEQ * DIM;

    float acc1[4][4] = {};
    float acc2[4][4] = {};

    const int lr = t >> 3;           // row 0..31 (i)
    const int lc = (t & 7) << 3;     // col 0..56 step 8

    for (int i0 = 0; i0 < SEQ; i0 += 32) {
        // dis tile -> dw (apply exp)
        {
            const float* src = &disb[(size_t)(i0 + lr) * SEQ + j0 + lc];
            float4 v0 = *(const float4*)&src[0];
            float4 v1 = *(const float4*)&src[4];
            dw_s[lr][lc + 0] = __expf(coef * v0.x);
            dw_s[lr][lc + 1] = __expf(coef * v0.y);
            dw_s[lr][lc + 2] = __expf(coef * v0.z);
            dw_s[lr][lc + 3] = __expf(coef * v0.w);
            dw_s[lr][lc + 4] = __expf(coef * v1.x);
            dw_s[lr][lc + 5] = __expf(coef * v1.y);
            dw_s[lr][lc + 6] = __expf(coef * v1.z);
            dw_s[lr][lc + 7] = __expf(coef * v1.w);
        }
        // kwv / kw tiles
        {
            const float* s1 = &kwvb[(size_t)(i0 + lr) * DIM + d0 + lc];
            const float* s2 = &kwb [(size_t)(i0 + lr) * DIM + d0 + lc];
            *(float4*)&x1_s[lr][lc]     = *(const float4*)&s1[0];
            *(float4*)&x1_s[lr][lc + 4] = *(const float4*)&s1[4];
            *(float4*)&x2_s[lr][lc]     = *(const float4*)&s2[0];
            *(float4*)&x2_s[lr][lc + 4] = *(const float4*)&s2[4];
        }
        __syncthreads();

        #pragma unroll
        for (int kk = 0; kk < 32; kk++) {
            float4 af = *(float4*)&dw_s[kk][ty * 4];
            float4 b1 = *(float4*)&x1_s[kk][tx * 4];
            float4 b2 = *(float4*)&x2_s[kk][tx * 4];
            float a[4] = {af.x, af.y, af.z, af.w};
            float p[4] = {b1.x, b1.y, b1.z, b1.w};
            float q[4] = {b2.x, b2.y, b2.z, b2.w};
            #pragma unroll
            for (int i = 0; i < 4; i++) {
                #pragma unroll
                for (int j = 0; j < 4; j++) {
                    acc1[i][j] = fmaf(a[i], p[j], acc1[i][j]);
                    acc2[i][j] = fmaf(a[i], q[j], acc2[i][j]);
                }
            }
        }
        __syncthreads();
    }

    // epilogue: out = sig * acc1/acc2
    const float* sigb = g_sig + (size_t)b * SEQ * DIM;
    float* outb = out + (size_t)b * SEQ * DIM;
    #pragma unroll
    for (int i = 0; i < 4; i++) {
        int idx = (j0 + ty * 4 + i) * DIM + d0 + tx * 4;
        float4 sg = *(const float4*)&sigb[idx];
        float4 o;
        o.x = sg.x * (acc1[i][0] / acc2[i][0]);
        o.y = sg.y * (acc1[i][1] / acc2[i][1]);
        o.z = sg.z * (acc1[i][2] / acc2[i][2]);
        o.w = sg.w * (acc1[i][3] / acc2[i][3]);
        *(float4*)&outb[idx] = o;
    }
}

// ---------------------------------------------------------------------------
// Launch
// ---------------------------------------------------------------------------
extern "C" void kernel_launch(void* const* d_in, const int* in_sizes, int n_in,
                              void* d_out, int out_size) {
    const float* x     = (const float*)d_in[0];   // [8,2048,512]
    const float* dis   = (const float*)d_in[1];   // [8,2048,2048]
    const float* Wq    = (const float*)d_in[2];   // [512,512]
    const float* Wk    = (const float*)d_in[3];
    const float* Wv    = (const float*)d_in[4];
    const float* alpha = (const float*)d_in[5];   // scalar
    float* out = (float*)d_out;

    // Resolve device-global scratch addresses (no allocation).
    float *p_sig, *p_kw, *p_kwv, *p_wt;
    cudaGetSymbolAddress((void**)&p_sig, g_sig);
    cudaGetSymbolAddress((void**)&p_kw,  g_kw);
    cudaGetSymbolAddress((void**)&p_kwv, g_kwv);
    cudaGetSymbolAddress((void**)&p_wt,  g_wt);

    // 1) transpose weights
    {
        dim3 grid(DIM / 32, DIM / 32, 3), block(32, 8);
        transpose_w_kernel<<<grid, block>>>(Wq, Wk, Wv);
    }
    // 2) QKV projections with fused elementwise
    {
        dim3 grid(DIM / 64, M_TOT / 64), block(256);
        gemm_qkv_kernel<0><<<grid, block>>>(x, p_wt + 0 * DIM * DIM, p_sig, nullptr);
        gemm_qkv_kernel<1><<<grid, block>>>(x, p_wt + 1 * DIM * DIM, p_kw,  nullptr);
        gemm_qkv_kernel<2><<<grid, block>>>(x, p_wt + 2 * DIM * DIM, p_kwv, p_kw);
    }
    // 3) main fused attention GEMM
    {
        dim3 grid(DIM / 64, SEQ / 64, BATCH), block(256);
        attn_kernel<<<grid, block>>>(dis, alpha, out);
    }
}

// round 2
// speedup vs baseline: 2.8370x; 2.8370x over previous
#include <cuda_runtime.h>
#include <math.h>
#include <stdint.h>

#define BATCH 8
#define SEQ   2048
#define DIM   512
#define M_TOT (BATCH * SEQ)   // 16384
#define NCAT  (3 * DIM)       // 1536

// Scratch (device globals: allocation-free per harness rules)
__device__ float g_sig[M_TOT * DIM];                 // sigmoid(q)
__device__ float g_kw [M_TOT * DIM];                 // exp(k)
__device__ float g_v  [M_TOT * DIM];                 // raw v
__device__ float g_dw [(size_t)BATCH * SEQ * SEQ];   // exp(coef*dis), tf32-rounded
__device__ float g_wt [DIM * NCAT];                  // [k][WqT|WkT|WvT]

// ---------------------------------------------------------------------------
// tf32 helpers
// ---------------------------------------------------------------------------
__device__ __forceinline__ uint32_t f2tf32(float x) {
    uint32_t u;
    asm("cvt.rna.tf32.f32 %0, %1;" : "=r"(u) : "f"(x));
    return u;
}
__device__ __forceinline__ float f2tf32f(float x) { return __uint_as_float(f2tf32(x)); }

__device__ __forceinline__ void mma8(float* c, const uint32_t* a, const uint32_t* b) {
    asm volatile(
        "mma.sync.aligned.m16n8k8.row.col.f32.tf32.tf32.f32 "
        "{%0,%1,%2,%3},{%4,%5,%6,%7},{%8,%9},{%0,%1,%2,%3};"
        : "+f"(c[0]), "+f"(c[1]), "+f"(c[2]), "+f"(c[3])
        : "r"(a[0]), "r"(a[1]), "r"(a[2]), "r"(a[3]), "r"(b[0]), "r"(b[1]));
}

// ---------------------------------------------------------------------------
// Transpose + concat weights: g_wt[k][z*512 + n] = W_z[n][k]
// grid (16, 16, 3), block (32, 8)
// ---------------------------------------------------------------------------
__global__ void transpose_w_kernel(const float* __restrict__ Wq,
                                   const float* __restrict__ Wk,
                                   const float* __restrict__ Wv) {
    __shared__ float tile[32][33];
    const float* W = (blockIdx.z == 0) ? Wq : (blockIdx.z == 1) ? Wk : Wv;

    int x = blockIdx.x * 32 + threadIdx.x;   // k
    int y = blockIdx.y * 32 + threadIdx.y;   // n
    #pragma unroll
    for (int j = 0; j < 32; j += 8)
        tile[threadIdx.y + j][threadIdx.x] = W[(y + j) * DIM + x];
    __syncthreads();
    int xo = blockIdx.y * 32 + threadIdx.x;  // n
    int yo = blockIdx.x * 32 + threadIdx.y;  // k
    #pragma unroll
    for (int j = 0; j < 32; j += 8)
        g_wt[(yo + j) * NCAT + blockIdx.z * DIM + xo] = tile[threadIdx.x][threadIdx.y + j];
}

// ---------------------------------------------------------------------------
// dw precompute: g_dw = tf32(exp(-alpha*11*dis)); float4 elementwise
// grid 32768, block 256  (8*2048*2048/4 = 8388608 float4)
// ---------------------------------------------------------------------------
__global__ void dw_kernel(const float* __restrict__ dis,
                          const float* __restrict__ alpha_p) {
    const float coef = -(alpha_p[0] * 11.0f);   // -alpha*log2(2048)
    size_t i = ((size_t)blockIdx.x * blockDim.x + threadIdx.x) * 4;
    float4 v = *(const float4*)(dis + i);
    float4 o;
    o.x = f2tf32f(__expf(coef * v.x));
    o.y = f2tf32f(__expf(coef * v.y));
    o.z = f2tf32f(__expf(coef * v.z));
    o.w = f2tf32f(__expf(coef * v.w));
    *(float4*)(g_dw + i) = o;
}

// ---------------------------------------------------------------------------
// QKV GEMM (tf32 mma): C[m,n] = sum_k x[m,k] * g_wt[k,n], M=16384, N=1536, K=512
// BM=128, BN=64, BK=32, 256 threads (8 warps, 4x2), warp tile 32x32.
// Epilogue by n-range: sigmoid -> g_sig, exp -> g_kw, raw -> g_v
// grid (24, 128)
// ---------------------------------------------------------------------------
__global__ void __launch_bounds__(256)
qkv_kernel(const float* __restrict__ x) {
    __shared__ float As[128][36];   // [m][k], stride%32==4
    __shared__ float Bs[32][72];    // [k][n], stride%32==8

    const int t = threadIdx.x, l = t & 31, w = t >> 5;
    const int wm = w >> 1, wn = w & 1;
    const int m0 = blockIdx.y * 128, n0 = blockIdx.x * 64;

    float acc[2][4][4] = {};

    for (int k0 = 0; k0 < DIM; k0 += 32) {
        {   // A tile: 128x32 -> 4 float4/thread
            int ar = t >> 1;
            const float* src = &x[(size_t)(m0 + ar) * DIM + k0];
            #pragma unroll
            for (int it = 0; it < 4; it++) {
                int c = ((t & 1) + it * 2) * 4;
                float4 v = *(const float4*)&src[c];
                As[ar][c + 0] = f2tf32f(v.x);
                As[ar][c + 1] = f2tf32f(v.y);
                As[ar][c + 2] = f2tf32f(v.z);
                As[ar][c + 3] = f2tf32f(v.w);
            }
        }
        {   // B tile: 32x64 -> 2 float4/thread
            int br = t >> 3;
            const float* src = &g_wt[(size_t)(k0 + br) * NCAT + n0];
            #pragma unroll
            for (int it = 0; it < 2; it++) {
                int c = ((t & 7) + it * 8) * 4;
                float4 v = *(const float4*)&src[c];
                Bs[br][c + 0] = f2tf32f(v.x);
                Bs[br][c + 1] = f2tf32f(v.y);
                Bs[br][c + 2] = f2tf32f(v.z);
                Bs[br][c + 3] = f2tf32f(v.w);
            }
        }
        __syncthreads();

        #pragma unroll
        for (int ks = 0; ks < 4; ks++) {
            const int kk = ks * 8;
            uint32_t a[2][4], b[4][2];
            #pragma unroll
            for (int mt = 0; mt < 2; mt++) {
                int mb = wm * 32 + mt * 16 + (l >> 2);
                a[mt][0] = __float_as_uint(As[mb    ][kk + (l & 3)]);
                a[mt][1] = __float_as_uint(As[mb + 8][kk + (l & 3)]);
                a[mt][2] = __float_as_uint(As[mb    ][kk + 4 + (l & 3)]);
                a[mt][3] = __float_as_uint(As[mb + 8][kk + 4 + (l & 3)]);
            }
            #pragma unroll
            for (int nt = 0; nt < 4; nt++) {
                int nb = wn * 32 + nt * 8 + (l >> 2);
                b[nt][0] = __float_as_uint(Bs[kk + (l & 3)][nb]);
                b[nt][1] = __float_as_uint(Bs[kk + 4 + (l & 3)][nb]);
            }
            #pragma unroll
            for (int mt = 0; mt < 2; mt++)
                #pragma unroll
                for (int nt = 0; nt < 4; nt++)
                    mma8(acc[mt][nt], a[mt], b[nt]);
        }
        __syncthreads();
    }

    // epilogue
    const int type = n0 >> 9;                  // 0: q, 1: k, 2: v
    float* dst = (type == 0) ? g_sig : (type == 1) ? g_kw : g_v;
    const int nl0 = n0 - type * 512;

    #pragma unroll
    for (int mt = 0; mt < 2; mt++) {
        #pragma unroll
        for (int nt = 0; nt < 4; nt++) {
            int row = m0 + wm * 32 + mt * 16 + (l >> 2);
            int col = nl0 + wn * 32 + nt * 8 + 2 * (l & 3);
            float c0 = acc[mt][nt][0], c1 = acc[mt][nt][1];
            float c2 = acc[mt][nt][2], c3 = acc[mt][nt][3];
            if (type == 0) {
                c0 = 1.0f / (1.0f + __expf(-c0));
                c1 = 1.0f / (1.0f + __expf(-c1));
                c2 = 1.0f / (1.0f + __expf(-c2));
                c3 = 1.0f / (1.0f + __expf(-c3));
            } else if (type == 1) {
                c0 = __expf(c0); c1 = __expf(c1);
                c2 = __expf(c2); c3 = __expf(c3);
            }
            *(float2*)&dst[(size_t)row * DIM + col]       = make_float2(c0, c1);
            *(float2*)&dst[(size_t)(row + 8) * DIM + col] = make_float2(c2, c3);
        }
    }
}

// ---------------------------------------------------------------------------
// Attention GEMM (tf32 mma, dual accumulator):
//   w1[j,d] = sum_i dw[i,j] * (kw*v)[i,d]
//   w2[j,d] = sum_i dw[i,j] * kw[i,d]
//   out[j,d] = sig[j,d] * w1/w2
// BM=128 (j), BN=64 (d), BK=32 (i), 256 threads, warp tile 32x32.
// grid (8, 16, 8)
// ---------------------------------------------------------------------------
__global__ void __launch_bounds__(256)
attn_kernel(float* __restrict__ out) {
    __shared__ float As [32][136];  // dw [i][j], stride%32==8
    __shared__ float B1s[32][72];   // kw*v [i][d]
    __shared__ float B2s[32][72];   // kw   [i][d]

    const int t = threadIdx.x, l = t & 31, w = t >> 5;
    const int wm = w >> 1, wn = w & 1;
    const int bb = blockIdx.z;
    const int j0 = blockIdx.y * 128, d0 = blockIdx.x * 64;

    const float* dwb = g_dw + (size_t)bb * SEQ * SEQ;
    const float* kwb = g_kw + (size_t)bb * SEQ * DIM;
    const float* vb  = g_v  + (size_t)bb * SEQ * DIM;

    float acc1[2][4][4] = {};
    float acc2[2][4][4] = {};

    for (int i0 = 0; i0 < SEQ; i0 += 32) {
        {   // dw tile [32 i][128 j]: 4 float4/thread (pre-rounded tf32)
            int r = t >> 3;
            const float* src = &dwb[(size_t)(i0 + r) * SEQ + j0];
            #pragma unroll
            for (int it = 0; it < 4; it++) {
                int c = ((t & 7) + it * 8) * 4;
                *(float4*)&As[r][c] = *(const float4*)&src[c];
            }
        }
        {   // kw & v tiles [32 i][64 d]: 2 float4/thread each
            int r = t >> 3;
            const float* s2 = &kwb[(size_t)(i0 + r) * DIM + d0];
            const float* sv = &vb [(size_t)(i0 + r) * DIM + d0];
            #pragma unroll
            for (int it = 0; it < 2; it++) {
                int c = ((t & 7) + it * 8) * 4;
                float4 kwv = *(const float4*)&s2[c];
                float4 vv  = *(const float4*)&sv[c];
                B2s[r][c + 0] = f2tf32f(kwv.x);
                B2s[r][c + 1] = f2tf32f(kwv.y);
                B2s[r][c + 2] = f2tf32f(kwv.z);
                B2s[r][c + 3] = f2tf32f(kwv.w);
                B1s[r][c + 0] = f2tf32f(kwv.x * vv.x);
                B1s[r][c + 1] = f2tf32f(kwv.y * vv.y);
                B1s[r][c + 2] = f2tf32f(kwv.z * vv.z);
                B1s[r][c + 3] = f2tf32f(kwv.w * vv.w);
            }
        }
        __syncthreads();

        #pragma unroll
        for (int ks = 0; ks < 4; ks++) {
            const int kk = ks * 8;
            uint32_t a[2][4], b1[4][2], b2[4][2];
            #pragma unroll
            for (int mt = 0; mt < 2; mt++) {
                int mb = wm * 32 + mt * 16 + (l >> 2);
                // A[j][i] = As[i][j]  (transposed read)
                a[mt][0] = __float_as_uint(As[kk + (l & 3)    ][mb    ]);
                a[mt][1] = __float_as_uint(As[kk + (l & 3)    ][mb + 8]);
                a[mt][2] = __float_as_uint(As[kk + 4 + (l & 3)][mb    ]);
                a[mt][3] = __float_as_uint(As[kk + 4 + (l & 3)][mb + 8]);
            }
            #pragma unroll
            for (int nt = 0; nt < 4; nt++) {
                int nb = wn * 32 + nt * 8 + (l >> 2);
                b1[nt][0] = __float_as_uint(B1s[kk + (l & 3)    ][nb]);
                b1[nt][1] = __float_as_uint(B1s[kk + 4 + (l & 3)][nb]);
                b2[nt][0] = __float_as_uint(B2s[kk + (l & 3)    ][nb]);
                b2[nt][1] = __float_as_uint(B2s[kk + 4 + (l & 3)][nb]);
            }
            #pragma unroll
            for (int mt = 0; mt < 2; mt++) {
                #pragma unroll
                for (int nt = 0; nt < 4; nt++) {
                    mma8(acc1[mt][nt], a[mt], b1[nt]);
                    mma8(acc2[mt][nt], a[mt], b2[nt]);
                }
            }
        }
        __syncthreads();
    }

    // epilogue: out = sig * w1/w2
    const float* sigb = g_sig + (size_t)bb * SEQ * DIM;
    float* outb = out + (size_t)bb * SEQ * DIM;
    #pragma unroll
    for (int mt = 0; mt < 2; mt++) {
        #pragma unroll
        for (int nt = 0; nt < 4; nt++) {
            int jr = j0 + wm * 32 + mt * 16 + (l >> 2);
            int dc = d0 + wn * 32 + nt * 8 + 2 * (l & 3);
            size_t i0x = (size_t)jr * DIM + dc;
            size_t i1x = (size_t)(jr + 8) * DIM + dc;
            float2 s0 = *(const float2*)&sigb[i0x];
            float2 s1 = *(const float2*)&sigb[i1x];
            float2 o0, o1;
            o0.x = s0.x * __fdividef(acc1[mt][nt][0], acc2[mt][nt][0]);
            o0.y = s0.y * __fdividef(acc1[mt][nt][1], acc2[mt][nt][1]);
            o1.x = s1.x * __fdividef(acc1[mt][nt][2], acc2[mt][nt][2]);
            o1.y = s1.y * __fdividef(acc1[mt][nt][3], acc2[mt][nt][3]);
            *(float2*)&outb[i0x] = o0;
            *(float2*)&outb[i1x] = o1;
        }
    }
}

// ---------------------------------------------------------------------------
// Launch
// ---------------------------------------------------------------------------
extern "C" void kernel_launch(void* const* d_in, const int* in_sizes, int n_in,
                              void* d_out, int out_size) {
    const float* x     = (const float*)d_in[0];   // [8,2048,512]
    const float* dis   = (const float*)d_in[1];   // [8,2048,2048]
    const float* Wq    = (const float*)d_in[2];
    const float* Wk    = (const float*)d_in[3];
    const float* Wv    = (const float*)d_in[4];
    const float* alpha = (const float*)d_in[5];
    float* out = (float*)d_out;

    {   // weights transpose+concat
        dim3 grid(DIM / 32, DIM / 32, 3), block(32, 8);
        transpose_w_kernel<<<grid, block>>>(Wq, Wk, Wv);
    }
    {   // dw precompute (independent of transpose/qkv)
        dw_kernel<<<32768, 256>>>(dis, alpha);
    }
    {   // fused QKV projection
        dim3 grid(NCAT / 64, M_TOT / 128), block(256);
        qkv_kernel<<<grid, block>>>(x);
    }
    {   // main dual-GEMM attention
        dim3 grid(DIM / 64, SEQ / 128, BATCH), block(256);
        attn_kernel<<<grid, block>>>(out);
    }
}

// round 6
// speedup vs baseline: 2.9617x; 1.0439x over previous
#include <cuda_runtime.h>
#include <math.h>
#include <stdint.h>

#define BATCH 8
#define SEQ   2048
#define DIM   512
#define M_TOT (BATCH * SEQ)   // 16384
#define NCAT  (3 * DIM)       // 1536

// Scratch (device globals)
__device__ float g_sig[M_TOT * DIM];                 // sigmoid(q)
__device__ float g_kw [M_TOT * DIM];                 // exp(k) -> tf32-rounded after fold
__device__ float g_v  [M_TOT * DIM];                 // v -> tf32(exp(k)*v) after fold
__device__ float g_dw [(size_t)BATCH * SEQ * SEQ];   // tf32(exp(coef*dis)) [b][i][j]
__device__ float g_wt [DIM * NCAT];                  // [k][WqT|WkT|WvT]

// ---------------------------------------------------------------------------
// helpers
// ---------------------------------------------------------------------------
__device__ __forceinline__ float f2tf32f(float x) {
    uint32_t u;
    asm("cvt.rna.tf32.f32 %0, %1;" : "=r"(u) : "f"(x));
    return __uint_as_float(u);
}
__device__ __forceinline__ uint32_t smem_u32(const void* p) {
    uint32_t a;
    asm("{ .reg .u64 t; cvta.to.shared.u64 t, %1; cvt.u32.u64 %0, t; }" : "=r"(a) : "l"(p));
    return a;
}

#define CP_ASYNC16(dst, src) \
    asm volatile("cp.async.cg.shared.global [%0], [%1], 16;" :: "r"(dst), "l"(src))
#define CP_COMMIT() asm volatile("cp.async.commit_group;" ::: "memory")
#define CP_WAIT(n)  asm volatile("cp.async.wait_group %0;" :: "n"(n) : "memory")

__device__ __forceinline__ void mma8(float* c, const uint32_t* a, const uint32_t* b) {
    asm volatile(
        "mma.sync.aligned.m16n8k8.row.col.f32.tf32.tf32.f32 "
        "{%0,%1,%2,%3},{%4,%5,%6,%7},{%8,%9},{%0,%1,%2,%3};"
        : "+f"(c[0]), "+f"(c[1]), "+f"(c[2]), "+f"(c[3])
        : "r"(a[0]), "r"(a[1]), "r"(a[2]), "r"(a[3]), "r"(b[0]), "r"(b[1]));
}

// ---------------------------------------------------------------------------
// Transpose + concat weights: g_wt[k][z*512 + n] = W_z[n][k]
// ---------------------------------------------------------------------------
__global__ void transpose_w_kernel(const float* __restrict__ Wq,
                                   const float* __restrict__ Wk,
                                   const float* __restrict__ Wv) {
    __shared__ float tile[32][33];
    const float* W = (blockIdx.z == 0) ? Wq : (blockIdx.z == 1) ? Wk : Wv;
    int x = blockIdx.x * 32 + threadIdx.x;
    int y = blockIdx.y * 32 + threadIdx.y;
    #pragma unroll
    for (int j = 0; j < 32; j += 8)
        tile[threadIdx.y + j][threadIdx.x] = W[(y + j) * DIM + x];
    __syncthreads();
    int xo = blockIdx.y * 32 + threadIdx.x;
    int yo = blockIdx.x * 32 + threadIdx.y;
    #pragma unroll
    for (int j = 0; j < 32; j += 8)
        g_wt[(yo + j) * NCAT + blockIdx.z * DIM + xo] = tile[threadIdx.x][threadIdx.y + j];
}

// ---------------------------------------------------------------------------
// dw precompute: g_dw = tf32(exp(coef*dis)); elementwise float4
// ---------------------------------------------------------------------------
__global__ void dw_kernel(const float* __restrict__ dis,
                          const float* __restrict__ alpha_p) {
    const float coef = -(alpha_p[0] * 11.0f);   // -alpha*log2(2048)
    size_t i = ((size_t)blockIdx.x * blockDim.x + threadIdx.x) * 4;
    float4 v = *(const float4*)(dis + i);
    float4 o;
    o.x = f2tf32f(__expf(coef * v.x));
    o.y = f2tf32f(__expf(coef * v.y));
    o.z = f2tf32f(__expf(coef * v.z));
    o.w = f2tf32f(__expf(coef * v.w));
    *(float4*)(g_dw + i) = o;
}

// ---------------------------------------------------------------------------
// fold: g_kw <- tf32(kw) (in place), g_v <- tf32(kw*v) (in place)
// ---------------------------------------------------------------------------
__global__ void fold_kernel() {
    size_t i = ((size_t)blockIdx.x * blockDim.x + threadIdx.x) * 4;
    float4 kw = *(const float4*)(g_kw + i);
    float4 vv = *(const float4*)(g_v + i);
    float4 a, b;
    a.x = f2tf32f(kw.x); a.y = f2tf32f(kw.y); a.z = f2tf32f(kw.z); a.w = f2tf32f(kw.w);
    b.x = f2tf32f(kw.x * vv.x); b.y = f2tf32f(kw.y * vv.y);
    b.z = f2tf32f(kw.z * vv.z); b.w = f2tf32f(kw.w * vv.w);
    *(float4*)(g_kw + i) = a;
    *(float4*)(g_v + i)  = b;
}

// ---------------------------------------------------------------------------
// QKV GEMM (tf32 mma.sync): C[m,n] = sum_k x[m,k]*g_wt[k,n]; M=16384,N=1536,K=512
// ---------------------------------------------------------------------------
__global__ void __launch_bounds__(256)
qkv_kernel(const float* __restrict__ x) {
    __shared__ float As[128][36];
    __shared__ float Bs[32][72];

    const int t = threadIdx.x, l = t & 31, w = t >> 5;
    const int wm = w >> 1, wn = w & 1;
    const int m0 = blockIdx.y * 128, n0 = blockIdx.x * 64;

    float acc[2][4][4] = {};

    for (int k0 = 0; k0 < DIM; k0 += 32) {
        {
            int ar = t >> 1;
            const float* src = &x[(size_t)(m0 + ar) * DIM + k0];
            #pragma unroll
            for (int it = 0; it < 4; it++) {
                int c = ((t & 1) + it * 2) * 4;
                float4 v = *(const float4*)&src[c];
                As[ar][c + 0] = f2tf32f(v.x);
                As[ar][c + 1] = f2tf32f(v.y);
                As[ar][c + 2] = f2tf32f(v.z);
                As[ar][c + 3] = f2tf32f(v.w);
            }
        }
        {
            int br = t >> 3;
            const float* src = &g_wt[(size_t)(k0 + br) * NCAT + n0];
            #pragma unroll
            for (int it = 0; it < 2; it++) {
                int c = ((t & 7) + it * 8) * 4;
                float4 v = *(const float4*)&src[c];
                Bs[br][c + 0] = f2tf32f(v.x);
                Bs[br][c + 1] = f2tf32f(v.y);
                Bs[br][c + 2] = f2tf32f(v.z);
                Bs[br][c + 3] = f2tf32f(v.w);
            }
        }
        __syncthreads();

        #pragma unroll
        for (int ks = 0; ks < 4; ks++) {
            const int kk = ks * 8;
            uint32_t a[2][4], b[4][2];
            #pragma unroll
            for (int mt = 0; mt < 2; mt++) {
                int mb = wm * 32 + mt * 16 + (l >> 2);
                a[mt][0] = __float_as_uint(As[mb    ][kk + (l & 3)]);
                a[mt][1] = __float_as_uint(As[mb + 8][kk + (l & 3)]);
                a[mt][2] = __float_as_uint(As[mb    ][kk + 4 + (l & 3)]);
                a[mt][3] = __float_as_uint(As[mb + 8][kk + 4 + (l & 3)]);
            }
            #pragma unroll
            for (int nt = 0; nt < 4; nt++) {
                int nb = wn * 32 + nt * 8 + (l >> 2);
                b[nt][0] = __float_as_uint(Bs[kk + (l & 3)][nb]);
                b[nt][1] = __float_as_uint(Bs[kk + 4 + (l & 3)][nb]);
            }
            #pragma unroll
            for (int mt = 0; mt < 2; mt++)
                #pragma unroll
                for (int nt = 0; nt < 4; nt++)
                    mma8(acc[mt][nt], a[mt], b[nt]);
        }
        __syncthreads();
    }

    const int type = n0 >> 9;
    float* dst = (type == 0) ? g_sig : (type == 1) ? g_kw : g_v;
    const int nl0 = n0 - type * 512;

    #pragma unroll
    for (int mt = 0; mt < 2; mt++) {
        #pragma unroll
        for (int nt = 0; nt < 4; nt++) {
            int row = m0 + wm * 32 + mt * 16 + (l >> 2);
            int col = nl0 + wn * 32 + nt * 8 + 2 * (l & 3);
            float c0 = acc[mt][nt][0], c1 = acc[mt][nt][1];
            float c2 = acc[mt][nt][2], c3 = acc[mt][nt][3];
            if (type == 0) {
                c0 = 1.0f / (1.0f + __expf(-c0));
                c1 = 1.0f / (1.0f + __expf(-c1));
                c2 = 1.0f / (1.0f + __expf(-c2));
                c3 = 1.0f / (1.0f + __expf(-c3));
            } else if (type == 1) {
                c0 = __expf(c0); c1 = __expf(c1);
                c2 = __expf(c2); c3 = __expf(c3);
            }
            *(float2*)&dst[(size_t)row * DIM + col]       = make_float2(c0, c1);
            *(float2*)&dst[(size_t)(row + 8) * DIM + col] = make_float2(c2, c3);
        }
    }
}

// ---------------------------------------------------------------------------
// Attention dual-GEMM (mma.sync tf32, cp.async 2-stage pipeline)
//   acc1[j,d] += dw[i,j] * kwv[i,d] ; acc2[j,d] += dw[i,j] * kw[i,d]
// BM=128 (j), BN=64 (d), BK=32 (i). 128 threads = 4 warps (wm 2 x wn 2),
// warp tile 64x32, dual acc. grid (8, 16, 8).
// smem/stage: A 32x136, B1 32x72, B2 32x72 floats.
// ---------------------------------------------------------------------------
#define AST 136
#define BST 72
#define STG_A (32 * AST)                   // 4352 floats
#define STG_B (32 * BST)                   // 2304 floats
#define STG   (STG_A + 2 * STG_B)          // 8960 floats
#define ATTN_SMEM (2 * STG * 4)            // 71680 bytes
#define N_ITILE (SEQ / 32)                 // 64

__global__ void __launch_bounds__(128)
attn_kernel(float* __restrict__ out) {
    extern __shared__ float sm[];
    const uint32_t sb = smem_u32(sm);
    const int t = threadIdx.x, l = t & 31, w = t >> 5;
    const int wm = w >> 1, wn = w & 1;
    const int b = blockIdx.z, j0 = blockIdx.y * 128, d0 = blockIdx.x * 64;

    const float* dwb = g_dw + (size_t)b * SEQ * SEQ;   // [i][j]
    const float* kwb = g_kw + (size_t)b * SEQ * DIM;   // [i][d]  tf32(kw)
    const float* kvb = g_v  + (size_t)b * SEQ * DIM;   // [i][d]  tf32(kw*v)

    // load geometry: 128 threads; row = t>>2 (0..31), chunk base = t&3
    // NOTE: base pointers carry ONLY the row offset; the chunk index (which
    // includes lc) supplies the full column offset.  (R4 bug: lc was counted
    // in both -> OOB.)
    const int lr = t >> 2;
    const int lc = t & 3;
    const float* srcA  = dwb + (size_t)lr * SEQ + j0;
    const float* srcB1 = kvb + (size_t)lr * DIM + d0;
    const float* srcB2 = kwb + (size_t)lr * DIM + d0;

    float acc1[4][4][4] = {};
    float acc2[4][4][4] = {};

    auto load_stage = [&](int tile, int stage) {
        const size_t iofs = (size_t)tile * 32;
        const uint32_t s0 = sb + stage * (STG * 4);
        const uint32_t aBase  = s0 + (lr * AST) * 4;
        const uint32_t b1Base = s0 + (STG_A + lr * BST) * 4;
        const uint32_t b2Base = s0 + (STG_A + STG_B + lr * BST) * 4;
        #pragma unroll
        for (int it = 0; it < 8; it++) {        // A: 32 chunks/row, 4 thr/row
            int ch = lc + it * 4;
            CP_ASYNC16(aBase + ch * 16, srcA + iofs * SEQ + ch * 4);
        }
        #pragma unroll
        for (int it = 0; it < 4; it++) {        // B: 16 chunks/row
            int ch = lc + it * 4;
            CP_ASYNC16(b1Base + ch * 16, srcB1 + iofs * DIM + ch * 4);
            CP_ASYNC16(b2Base + ch * 16, srcB2 + iofs * DIM + ch * 4);
        }
        CP_COMMIT();
    };

    auto compute_stage = [&](int stage) {
        const float* As = sm + stage * STG;
        const float* B1 = As + STG_A;
        const float* B2 = B1 + STG_B;
        #pragma unroll
        for (int ks = 0; ks < 4; ks++) {
            const int kk = ks * 8;
            uint32_t a[4][4], b1[4][2], b2[4][2];
            const int k0r = (kk + (l & 3)) * AST;
            const int k4r = (kk + 4 + (l & 3)) * AST;
            #pragma unroll
            for (int mt = 0; mt < 4; mt++) {
                int mb = wm * 64 + mt * 16 + (l >> 2);
                a[mt][0] = __float_as_uint(As[k0r + mb]);
                a[mt][1] = __float_as_uint(As[k0r + mb + 8]);
                a[mt][2] = __float_as_uint(As[k4r + mb]);
                a[mt][3] = __float_as_uint(As[k4r + mb + 8]);
            }
            const int k0b = (kk + (l & 3)) * BST;
            const int k4b = (kk + 4 + (l & 3)) * BST;
            #pragma unroll
            for (int nt = 0; nt < 4; nt++) {
                int nb = wn * 32 + nt * 8 + (l >> 2);
                b1[nt][0] = __float_as_uint(B1[k0b + nb]);
                b1[nt][1] = __float_as_uint(B1[k4b + nb]);
                b2[nt][0] = __float_as_uint(B2[k0b + nb]);
                b2[nt][1] = __float_as_uint(B2[k4b + nb]);
            }
            #pragma unroll
            for (int mt = 0; mt < 4; mt++) {
                #pragma unroll
                for (int nt = 0; nt < 4; nt++) {
                    mma8(acc1[mt][nt], a[mt], b1[nt]);
                    mma8(acc2[mt][nt], a[mt], b2[nt]);
                }
            }
        }
    };

    load_stage(0, 0);
    for (int tile = 0; tile < N_ITILE; tile++) {
        if (tile + 1 < N_ITILE) {
            load_stage(tile + 1, (tile + 1) & 1);
            CP_WAIT(1);
        } else {
            CP_WAIT(0);
        }
        __syncthreads();
        compute_stage(tile & 1);
        __syncthreads();
    }

    // epilogue: out = sig * acc1/acc2
    const float* sigb = g_sig + (size_t)b * SEQ * DIM;
    float* outb = out + (size_t)b * SEQ * DIM;
    #pragma unroll
    for (int mt = 0; mt < 4; mt++) {
        #pragma unroll
        for (int nt = 0; nt < 4; nt++) {
            int jr = j0 + wm * 64 + mt * 16 + (l >> 2);
            int dc = d0 + wn * 32 + nt * 8 + 2 * (l & 3);
            size_t i0x = (size_t)jr * DIM + dc;
            size_t i1x = (size_t)(jr + 8) * DIM + dc;
            float2 s0 = *(const float2*)&sigb[i0x];
            float2 s1 = *(const float2*)&sigb[i1x];
            float2 o0, o1;
            o0.x = s0.x * __fdividef(acc1[mt][nt][0], acc2[mt][nt][0]);
            o0.y = s0.y * __fdividef(acc1[mt][nt][1], acc2[mt][nt][1]);
            o1.x = s1.x * __fdividef(acc1[mt][nt][2], acc2[mt][nt][2]);
            o1.y = s1.y * __fdividef(acc1[mt][nt][3], acc2[mt][nt][3]);
            *(float2*)&outb[i0x] = o0;
            *(float2*)&outb[i1x] = o1;
        }
    }
}

// ---------------------------------------------------------------------------
// Launch
// ---------------------------------------------------------------------------
extern "C" void kernel_launch(void* const* d_in, const int* in_sizes, int n_in,
                              void* d_out, int out_size) {
    const float* x     = (const float*)d_in[0];
    const float* dis   = (const float*)d_in[1];
    const float* Wq    = (const float*)d_in[2];
    const float* Wk    = (const float*)d_in[3];
    const float* Wv    = (const float*)d_in[4];
    const float* alpha = (const float*)d_in[5];
    float* out = (float*)d_out;

    cudaFuncSetAttribute(attn_kernel, cudaFuncAttributeMaxDynamicSharedMemorySize, ATTN_SMEM);

    {   // weights transpose+concat
        dim3 grid(DIM / 32, DIM / 32, 3), block(32, 8);
        transpose_w_kernel<<<grid, block>>>(Wq, Wk, Wv);
    }
    {   // dw precompute (independent)
        dw_kernel<<<32768, 256>>>(dis, alpha);
    }
    {   // fused QKV projection
        dim3 grid(NCAT / 64, M_TOT / 128), block(256);
        qkv_kernel<<<grid, block>>>(x);
    }
    {   // fold kw*v + tf32 rounding (in place)
        fold_kernel<<<8192, 256>>>();
    }
    {   // pipelined dual-GEMM attention
        dim3 grid(DIM / 64, SEQ / 128, BATCH), block(128);
        attn_kernel<<<grid, block, ATTN_SMEM>>>(out);
    }
}

// round 7
// speedup vs baseline: 3.3918x; 1.1452x over previous
#include <cuda_runtime.h>
#include <math.h>
#include <stdint.h>

#define BATCH 8
#define SEQ   2048
#define DIM   512
#define M_TOT (BATCH * SEQ)   // 16384
#define NCAT  (3 * DIM)       // 1536

// Scratch (device globals)
__device__ float g_sig[M_TOT * DIM];                 // sigmoid(q)
__device__ float g_kw [M_TOT * DIM];                 // exp(k) -> tf32 after fold
__device__ float g_v  [M_TOT * DIM];                 // v -> tf32(exp(k)*v) after fold
__device__ float g_x  [M_TOT * DIM];                 // tf32(x)
__device__ float g_dw [(size_t)BATCH * SEQ * SEQ];   // tf32(exp(coef*dis)) [b][i][j]
__device__ float g_wt [DIM * NCAT];                  // tf32 [k][WqT|WkT|WvT]

// ---------------------------------------------------------------------------
// helpers
// ---------------------------------------------------------------------------
__device__ __forceinline__ float f2tf32f(float x) {
    uint32_t u;
    asm("cvt.rna.tf32.f32 %0, %1;" : "=r"(u) : "f"(x));
    return __uint_as_float(u);
}
__device__ __forceinline__ uint32_t smem_u32(const void* p) {
    uint32_t a;
    asm("{ .reg .u64 t; cvta.to.shared.u64 t, %1; cvt.u32.u64 %0, t; }" : "=r"(a) : "l"(p));
    return a;
}

#define CP_ASYNC16(dst, src) \
    asm volatile("cp.async.cg.shared.global [%0], [%1], 16;" :: "r"(dst), "l"(src))
#define CP_COMMIT() asm volatile("cp.async.commit_group;" ::: "memory")
#define CP_WAIT(n)  asm volatile("cp.async.wait_group %0;" :: "n"(n) : "memory")

__device__ __forceinline__ void mma8(float* c, const uint32_t* a, const uint32_t* b) {
    asm volatile(
        "mma.sync.aligned.m16n8k8.row.col.f32.tf32.tf32.f32 "
        "{%0,%1,%2,%3},{%4,%5,%6,%7},{%8,%9},{%0,%1,%2,%3};"
        : "+f"(c[0]), "+f"(c[1]), "+f"(c[2]), "+f"(c[3])
        : "r"(a[0]), "r"(a[1]), "r"(a[2]), "r"(a[3]), "r"(b[0]), "r"(b[1]));
}

// ---------------------------------------------------------------------------
// Transpose + concat weights (tf32-rounded): g_wt[k][z*512+n] = tf32(W_z[n][k])
// ---------------------------------------------------------------------------
__global__ void transpose_w_kernel(const float* __restrict__ Wq,
                                   const float* __restrict__ Wk,
                                   const float* __restrict__ Wv) {
    __shared__ float tile[32][33];
    const float* W = (blockIdx.z == 0) ? Wq : (blockIdx.z == 1) ? Wk : Wv;
    int x = blockIdx.x * 32 + threadIdx.x;
    int y = blockIdx.y * 32 + threadIdx.y;
    #pragma unroll
    for (int j = 0; j < 32; j += 8)
        tile[threadIdx.y + j][threadIdx.x] = W[(y + j) * DIM + x];
    __syncthreads();
    int xo = blockIdx.y * 32 + threadIdx.x;
    int yo = blockIdx.x * 32 + threadIdx.y;
    #pragma unroll
    for (int j = 0; j < 32; j += 8)
        g_wt[(yo + j) * NCAT + blockIdx.z * DIM + xo] =
            f2tf32f(tile[threadIdx.x][threadIdx.y + j]);
}

// ---------------------------------------------------------------------------
// x pre-round: g_x = tf32(x)
// ---------------------------------------------------------------------------
__global__ void xr_kernel(const float* __restrict__ x) {
    size_t i = ((size_t)blockIdx.x * blockDim.x + threadIdx.x) * 4;
    float4 v = *(const float4*)(x + i);
    float4 o;
    o.x = f2tf32f(v.x); o.y = f2tf32f(v.y); o.z = f2tf32f(v.z); o.w = f2tf32f(v.w);
    *(float4*)(g_x + i) = o;
}

// ---------------------------------------------------------------------------
// dw precompute: g_dw = tf32(exp(coef*dis))
// ---------------------------------------------------------------------------
__global__ void dw_kernel(const float* __restrict__ dis,
                          const float* __restrict__ alpha_p) {
    const float coef = -(alpha_p[0] * 11.0f);   // -alpha*log2(2048)
    size_t i = ((size_t)blockIdx.x * blockDim.x + threadIdx.x) * 4;
    float4 v = *(const float4*)(dis + i);
    float4 o;
    o.x = f2tf32f(__expf(coef * v.x));
    o.y = f2tf32f(__expf(coef * v.y));
    o.z = f2tf32f(__expf(coef * v.z));
    o.w = f2tf32f(__expf(coef * v.w));
    *(float4*)(g_dw + i) = o;
}

// ---------------------------------------------------------------------------
// fold: g_kw <- tf32(kw), g_v <- tf32(kw*v) (both in place)
// ---------------------------------------------------------------------------
__global__ void fold_kernel() {
    size_t i = ((size_t)blockIdx.x * blockDim.x + threadIdx.x) * 4;
    float4 kw = *(const float4*)(g_kw + i);
    float4 vv = *(const float4*)(g_v + i);
    float4 a, b;
    a.x = f2tf32f(kw.x); a.y = f2tf32f(kw.y); a.z = f2tf32f(kw.z); a.w = f2tf32f(kw.w);
    b.x = f2tf32f(kw.x * vv.x); b.y = f2tf32f(kw.y * vv.y);
    b.z = f2tf32f(kw.z * vv.z); b.w = f2tf32f(kw.w * vv.w);
    *(float4*)(g_kw + i) = a;
    *(float4*)(g_v + i)  = b;
}

// ---------------------------------------------------------------------------
// QKV GEMM: C[m,n] = sum_k g_x[m,k] * g_wt[k,n]; M=16384, N=1536, K=512
// BM=128, BN=128, BK=32; 128 threads = 4 warps (2x2), warp tile 64x64,
// single acc; 3-stage cp.async, one sync per K-tile. grid (12, 128).
// ---------------------------------------------------------------------------
#define QAST 36
#define QBST 136
#define QSTG_A (128 * QAST)            // 4608 floats
#define QSTG_B (32 * QBST)             // 4352 floats
#define QSTG   (QSTG_A + QSTG_B)       // 8960 floats
#define QKV_SMEM (3 * QSTG * 4)        // 107520 bytes
#define QN_KTILE (DIM / 32)            // 16

__global__ void __launch_bounds__(128)
qkv_kernel() {
    extern __shared__ float sm[];
    const uint32_t sb = smem_u32(sm);
    const int t = threadIdx.x, l = t & 31, w = t >> 5;
    const int wm = w >> 1, wn = w & 1;
    const int m0 = blockIdx.y * 128, n0 = blockIdx.x * 128;

    float acc[4][8][4] = {};

    auto load_stage = [&](int kt, int stage) {
        const int k0 = kt * 32;
        const uint32_t s0 = sb + stage * (QSTG * 4);
        // A: 128 rows x 32 k; thread t owns row t, 8 chunks of 16B
        const float* srcA = g_x + (size_t)(m0 + t) * DIM + k0;
        const uint32_t aBase = s0 + t * QAST * 4;
        #pragma unroll
        for (int ch = 0; ch < 8; ch++)
            CP_ASYNC16(aBase + ch * 16, srcA + ch * 4);
        // B: 32 rows x 128 n; row = t>>2, chunks (t&3)+4*it
        const int br = t >> 2;
        const float* srcB = g_wt + (size_t)br * NCAT + n0;   // k row added below
        const uint32_t bBase = s0 + (QSTG_A + br * QBST) * 4;
        #pragma unroll
        for (int it = 0; it < 8; it++) {
            int ch = (t & 3) + it * 4;
            CP_ASYNC16(bBase + ch * 16, srcB + (size_t)k0 * NCAT + ch * 4);
        }
        CP_COMMIT();
    };

    auto compute_stage = [&](int stage) {
        const float* As = sm + stage * QSTG;        // [m][k] stride 36
        const float* Bs = As + QSTG_A;              // [k][n] stride 136
        #pragma unroll
        for (int ks = 0; ks < 4; ks++) {
            const int kk = ks * 8;
            uint32_t a[4][4], b[8][2];
            #pragma unroll
            for (int mt = 0; mt < 4; mt++) {
                int mb = wm * 64 + mt * 16 + (l >> 2);
                a[mt][0] = __float_as_uint(As[(size_t)mb * QAST + kk + (l & 3)]);
                a[mt][1] = __float_as_uint(As[(size_t)(mb + 8) * QAST + kk + (l & 3)]);
                a[mt][2] = __float_as_uint(As[(size_t)mb * QAST + kk + 4 + (l & 3)]);
                a[mt][3] = __float_as_uint(As[(size_t)(mb + 8) * QAST + kk + 4 + (l & 3)]);
            }
            #pragma unroll
            for (int nt = 0; nt < 8; nt++) {
                int nb = wn * 64 + nt * 8 + (l >> 2);
                b[nt][0] = __float_as_uint(Bs[(size_t)(kk + (l & 3)) * QBST + nb]);
                b[nt][1] = __float_as_uint(Bs[(size_t)(kk + 4 + (l & 3)) * QBST + nb]);
            }
            #pragma unroll
            for (int mt = 0; mt < 4; mt++)
                #pragma unroll
                for (int nt = 0; nt < 8; nt++)
                    mma8(acc[mt][nt], a[mt], b[nt]);
        }
    };

    load_stage(0, 0);
    load_stage(1, 1);
    for (int kt = 0; kt < QN_KTILE; kt++) {
        if (kt == QN_KTILE - 1) { CP_WAIT(0); } else { CP_WAIT(1); }
        __syncthreads();
        compute_stage(kt % 3);
        if (kt + 2 < QN_KTILE) load_stage(kt + 2, (kt + 2) % 3);
    }

    // epilogue by n-segment
    const int type = n0 >> 9;                 // 0:q 1:k 2:v (BN=128 divides 512)
    float* dst = (type == 0) ? g_sig : (type == 1) ? g_kw : g_v;
    const int nl0 = n0 - type * 512;

    #pragma unroll
    for (int mt = 0; mt < 4; mt++) {
        #pragma unroll
        for (int nt = 0; nt < 8; nt++) {
            int row = m0 + wm * 64 + mt * 16 + (l >> 2);
            int col = nl0 + wn * 64 + nt * 8 + 2 * (l & 3);
            float c0 = acc[mt][nt][0], c1 = acc[mt][nt][1];
            float c2 = acc[mt][nt][2], c3 = acc[mt][nt][3];
            if (type == 0) {
                c0 = 1.0f / (1.0f + __expf(-c0));
                c1 = 1.0f / (1.0f + __expf(-c1));
                c2 = 1.0f / (1.0f + __expf(-c2));
                c3 = 1.0f / (1.0f + __expf(-c3));
            } else if (type == 1) {
                c0 = __expf(c0); c1 = __expf(c1);
                c2 = __expf(c2); c3 = __expf(c3);
            }
            *(float2*)&dst[(size_t)row * DIM + col]       = make_float2(c0, c1);
            *(float2*)&dst[(size_t)(row + 8) * DIM + col] = make_float2(c2, c3);
        }
    }
}

// ---------------------------------------------------------------------------
// Attention dual-GEMM (tf32 mma.sync, 3-stage cp.async, one sync/tile)
//   acc1[j,d] += dw[i,j]*kwv[i,d] ; acc2[j,d] += dw[i,j]*kw[i,d]
// BM=128 (j), BN=64 (d), BK=32 (i); 4 warps, warp tile 64x32 dual-acc.
// grid (8, 16, 8).
// ---------------------------------------------------------------------------
#define AST 136
#define BST 72
#define STG_A (32 * AST)                   // 4352 floats
#define STG_B (32 * BST)                   // 2304 floats
#define STG   (STG_A + 2 * STG_B)          // 8960 floats
#define ATTN_SMEM (3 * STG * 4)            // 107520 bytes
#define N_ITILE (SEQ / 32)                 // 64

__global__ void __launch_bounds__(128)
attn_kernel(float* __restrict__ out) {
    extern __shared__ float sm[];
    const uint32_t sb = smem_u32(sm);
    const int t = threadIdx.x, l = t & 31, w = t >> 5;
    const int wm = w >> 1, wn = w & 1;
    const int b = blockIdx.z, j0 = blockIdx.y * 128, d0 = blockIdx.x * 64;

    const float* dwb = g_dw + (size_t)b * SEQ * SEQ;   // [i][j]
    const float* kwb = g_kw + (size_t)b * SEQ * DIM;   // [i][d]  tf32(kw)
    const float* kvb = g_v  + (size_t)b * SEQ * DIM;   // [i][d]  tf32(kw*v)

    const int lr = t >> 2;          // 0..31 (i row)
    const int lc = t & 3;           // chunk phase
    const float* srcA  = dwb + (size_t)lr * SEQ + j0;
    const float* srcB1 = kvb + (size_t)lr * DIM + d0;
    const float* srcB2 = kwb + (size_t)lr * DIM + d0;

    float acc1[4][4][4] = {};
    float acc2[4][4][4] = {};

    auto load_stage = [&](int tile, int stage) {
        const size_t iofs = (size_t)tile * 32;
        const uint32_t s0 = sb + stage * (STG * 4);
        const uint32_t aBase  = s0 + (lr * AST) * 4;
        const uint32_t b1Base = s0 + (STG_A + lr * BST) * 4;
        const uint32_t b2Base = s0 + (STG_A + STG_B + lr * BST) * 4;
        #pragma unroll
        for (int it = 0; it < 8; it++) {        // A: 32 chunks/row, 4 thr/row
            int ch = lc + it * 4;
            CP_ASYNC16(aBase + ch * 16, srcA + iofs * SEQ + ch * 4);
        }
        #pragma unroll
        for (int it = 0; it < 4; it++) {        // B: 16 chunks/row
            int ch = lc + it * 4;
            CP_ASYNC16(b1Base + ch * 16, srcB1 + iofs * DIM + ch * 4);
            CP_ASYNC16(b2Base + ch * 16, srcB2 + iofs * DIM + ch * 4);
        }
        CP_COMMIT();
    };

    auto compute_stage = [&](int stage) {
        const float* As = sm + stage * STG;     // [i][j] stride 136
        const float* B1 = As + STG_A;           // [i][d] stride 72
        const float* B2 = B1 + STG_B;
        #pragma unroll
        for (int ks = 0; ks < 4; ks++) {
            const int kk = ks * 8;
            uint32_t a[4][4], b1[4][2], b2[4][2];
            const int k0r = (kk + (l & 3)) * AST;
            const int k4r = (kk + 4 + (l & 3)) * AST;
            #pragma unroll
            for (int mt = 0; mt < 4; mt++) {
                int mb = wm * 64 + mt * 16 + (l >> 2);
                a[mt][0] = __float_as_uint(As[k0r + mb]);
                a[mt][1] = __float_as_uint(As[k0r + mb + 8]);
                a[mt][2] = __float_as_uint(As[k4r + mb]);
                a[mt][3] = __float_as_uint(As[k4r + mb + 8]);
            }
            const int k0b = (kk + (l & 3)) * BST;
            const int k4b = (kk + 4 + (l & 3)) * BST;
            #pragma unroll
            for (int nt = 0; nt < 4; nt++) {
                int nb = wn * 32 + nt * 8 + (l >> 2);
                b1[nt][0] = __float_as_uint(B1[k0b + nb]);
                b1[nt][1] = __float_as_uint(B1[k4b + nb]);
                b2[nt][0] = __float_as_uint(B2[k0b + nb]);
                b2[nt][1] = __float_as_uint(B2[k4b + nb]);
            }
            #pragma unroll
            for (int mt = 0; mt < 4; mt++) {
                #pragma unroll
                for (int nt = 0; nt < 4; nt++) {
                    mma8(acc1[mt][nt], a[mt], b1[nt]);
                    mma8(acc2[mt][nt], a[mt], b2[nt]);
                }
            }
        }
    };

    load_stage(0, 0);
    load_stage(1, 1);
    for (int tile = 0; tile < N_ITILE; tile++) {
        if (tile == N_ITILE - 1) { CP_WAIT(0); } else { CP_WAIT(1); }
        __syncthreads();
        compute_stage(tile % 3);
        if (tile + 2 < N_ITILE) load_stage(tile + 2, (tile + 2) % 3);
    }

    // epilogue: out = sig * acc1/acc2
    const float* sigb = g_sig + (size_t)b * SEQ * DIM;
    float* outb = out + (size_t)b * SEQ * DIM;
    #pragma unroll
    for (int mt = 0; mt < 4; mt++) {
        #pragma unroll
        for (int nt = 0; nt < 4; nt++) {
            int jr = j0 + wm * 64 + mt * 16 + (l >> 2);
            int dc = d0 + wn * 32 + nt * 8 + 2 * (l & 3);
            size_t i0x = (size_t)jr * DIM + dc;
            size_t i1x = (size_t)(jr + 8) * DIM + dc;
            float2 s0 = *(const float2*)&sigb[i0x];
            float2 s1 = *(const float2*)&sigb[i1x];
            float2 o0, o1;
            o0.x = s0.x * __fdividef(acc1[mt][nt][0], acc2[mt][nt][0]);
            o0.y = s0.y * __fdividef(acc1[mt][nt][1], acc2[mt][nt][1]);
            o1.x = s1.x * __fdividef(acc1[mt][nt][2], acc2[mt][nt][2]);
            o1.y = s1.y * __fdividef(acc1[mt][nt][3], acc2[mt][nt][3]);
            *(float2*)&outb[i0x] = o0;
            *(float2*)&outb[i1x] = o1;
        }
    }
}

// ---------------------------------------------------------------------------
// Launch
// ---------------------------------------------------------------------------
extern "C" void kernel_launch(void* const* d_in, const int* in_sizes, int n_in,
                              void* d_out, int out_size) {
    const float* x     = (const float*)d_in[0];
    const float* dis   = (const float*)d_in[1];
    const float* Wq    = (const float*)d_in[2];
    const float* Wk    = (const float*)d_in[3];
    const float* Wv    = (const float*)d_in[4];
    const float* alpha = (const float*)d_in[5];
    float* out = (float*)d_out;

    cudaFuncSetAttribute(attn_kernel, cudaFuncAttributeMaxDynamicSharedMemorySize, ATTN_SMEM);
    cudaFuncSetAttribute(qkv_kernel,  cudaFuncAttributeMaxDynamicSharedMemorySize, QKV_SMEM);

    {   // weights transpose+concat (tf32)
        dim3 grid(DIM / 32, DIM / 32, 3), block(32, 8);
        transpose_w_kernel<<<grid, block>>>(Wq, Wk, Wv);
    }
    {   // x pre-round
        xr_kernel<<<8192, 256>>>(x);
    }
    {   // dw precompute
        dw_kernel<<<32768, 256>>>(dis, alpha);
    }
    {   // pipelined QKV projection
        dim3 grid(NCAT / 128, M_TOT / 128), block(128);
        qkv_kernel<<<grid, block, QKV_SMEM>>>();
    }
    {   // fold kw*v + tf32 rounding
        fold_kernel<<<8192, 256>>>();
    }
    {   // pipelined dual-GEMM attention
        dim3 grid(DIM / 64, SEQ / 128, BATCH), block(128);
        attn_kernel<<<grid, block, ATTN_SMEM>>>(out);
    }
}

// round 8
// speedup vs baseline: 3.4040x; 1.0036x over previous
#include <cuda_runtime.h>
#include <math.h>
#include <stdint.h>

#define BATCH 8
#define SEQ   2048
#define DIM   512
#define M_TOT (BATCH * SEQ)   // 16384
#define NCAT  (3 * DIM)       // 1536

// Scratch (device globals)
__device__ float g_sig[M_TOT * DIM];                 // sigmoid(q)
__device__ float g_kw [M_TOT * DIM];                 // exp(k) -> tf32 after fold
__device__ float g_v  [M_TOT * DIM];                 // v -> tf32(exp(k)*v) after fold
__device__ float g_x  [M_TOT * DIM];                 // tf32(x)
__device__ float g_dw [(size_t)BATCH * SEQ * SEQ];   // tf32(exp(coef*dis)) [b][i][j]
__device__ float g_wt [DIM * NCAT];                  // tf32 [k][WqT|WkT|WvT]

// ---------------------------------------------------------------------------
// helpers
// ---------------------------------------------------------------------------
__device__ __forceinline__ float f2tf32f(float x) {
    uint32_t u;
    asm("cvt.rna.tf32.f32 %0, %1;" : "=r"(u) : "f"(x));
    return __uint_as_float(u);
}
__device__ __forceinline__ uint32_t smem_u32(const void* p) {
    uint32_t a;
    asm("{ .reg .u64 t; cvta.to.shared.u64 t, %1; cvt.u32.u64 %0, t; }" : "=r"(a) : "l"(p));
    return a;
}

#define CP_ASYNC16(dst, src) \
    asm volatile("cp.async.cg.shared.global [%0], [%1], 16;" :: "r"(dst), "l"(src))
#define CP_COMMIT() asm volatile("cp.async.commit_group;" ::: "memory")
#define CP_WAIT(n)  asm volatile("cp.async.wait_group %0;" :: "n"(n) : "memory")

__device__ __forceinline__ void mma8(float* c, const uint32_t* a, const uint32_t* b) {
    asm volatile(
        "mma.sync.aligned.m16n8k8.row.col.f32.tf32.tf32.f32 "
        "{%0,%1,%2,%3},{%4,%5,%6,%7},{%8,%9},{%0,%1,%2,%3};"
        : "+f"(c[0]), "+f"(c[1]), "+f"(c[2]), "+f"(c[3])
        : "r"(a[0]), "r"(a[1]), "r"(a[2]), "r"(a[3]), "r"(b[0]), "r"(b[1]));
}

// ---------------------------------------------------------------------------
// Transpose + concat weights (tf32-rounded): g_wt[k][z*512+n] = tf32(W_z[n][k])
// ---------------------------------------------------------------------------
__global__ void transpose_w_kernel(const float* __restrict__ Wq,
                                   const float* __restrict__ Wk,
                                   const float* __restrict__ Wv) {
    __shared__ float tile[32][33];
    const float* W = (blockIdx.z == 0) ? Wq : (blockIdx.z == 1) ? Wk : Wv;
    int x = blockIdx.x * 32 + threadIdx.x;
    int y = blockIdx.y * 32 + threadIdx.y;
    #pragma unroll
    for (int j = 0; j < 32; j += 8)
        tile[threadIdx.y + j][threadIdx.x] = W[(y + j) * DIM + x];
    __syncthreads();
    int xo = blockIdx.y * 32 + threadIdx.x;
    int yo = blockIdx.x * 32 + threadIdx.y;
    #pragma unroll
    for (int j = 0; j < 32; j += 8)
        g_wt[(yo + j) * NCAT + blockIdx.z * DIM + xo] =
            f2tf32f(tile[threadIdx.x][threadIdx.y + j]);
}

// ---------------------------------------------------------------------------
// x pre-round: g_x = tf32(x)
// ---------------------------------------------------------------------------
__global__ void xr_kernel(const float* __restrict__ x) {
    size_t i = ((size_t)blockIdx.x * blockDim.x + threadIdx.x) * 4;
    float4 v = *(const float4*)(x + i);
    float4 o;
    o.x = f2tf32f(v.x); o.y = f2tf32f(v.y); o.z = f2tf32f(v.z); o.w = f2tf32f(v.w);
    *(float4*)(g_x + i) = o;
}

// ---------------------------------------------------------------------------
// dw precompute: g_dw = tf32(exp(coef*dis))
// ---------------------------------------------------------------------------
__global__ void dw_kernel(const float* __restrict__ dis,
                          const float* __restrict__ alpha_p) {
    const float coef = -(alpha_p[0] * 11.0f);   // -alpha*log2(2048)
    size_t i = ((size_t)blockIdx.x * blockDim.x + threadIdx.x) * 4;
    float4 v = *(const float4*)(dis + i);
    float4 o;
    o.x = f2tf32f(__expf(coef * v.x));
    o.y = f2tf32f(__expf(coef * v.y));
    o.z = f2tf32f(__expf(coef * v.z));
    o.w = f2tf32f(__expf(coef * v.w));
    *(float4*)(g_dw + i) = o;
}

// ---------------------------------------------------------------------------
// fold: g_kw <- tf32(kw), g_v <- tf32(kw*v) (both in place)
// ---------------------------------------------------------------------------
__global__ void fold_kernel() {
    size_t i = ((size_t)blockIdx.x * blockDim.x + threadIdx.x) * 4;
    float4 kw = *(const float4*)(g_kw + i);
    float4 vv = *(const float4*)(g_v + i);
    float4 a, b;
    a.x = f2tf32f(kw.x); a.y = f2tf32f(kw.y); a.z = f2tf32f(kw.z); a.w = f2tf32f(kw.w);
    b.x = f2tf32f(kw.x * vv.x); b.y = f2tf32f(kw.y * vv.y);
    b.z = f2tf32f(kw.z * vv.z); b.w = f2tf32f(kw.w * vv.w);
    *(float4*)(g_kw + i) = a;
    *(float4*)(g_v + i)  = b;
}

// ---------------------------------------------------------------------------
// QKV GEMM: C[m,n] = sum_k g_x[m,k] * g_wt[k,n]; M=16384, N=1536, K=512
// BM=256, BN=128, BK=32; 256 threads = 8 warps (4x2), warp tile 64x64,
// 3-stage cp.async, one sync per K-tile. grid (12, 64).
// ---------------------------------------------------------------------------
#define QAST 36
#define QBST 136
#define QSTG_A (256 * QAST)            // 9216 floats
#define QSTG_B (32 * QBST)             // 4352 floats
#define QSTG   (QSTG_A + QSTG_B)       // 13568 floats
#define QKV_SMEM (3 * QSTG * 4)        // 162816 bytes
#define QN_KTILE (DIM / 32)            // 16

__global__ void __launch_bounds__(256)
qkv_kernel() {
    extern __shared__ float sm[];
    const uint32_t sb = smem_u32(sm);
    const int t = threadIdx.x, l = t & 31, w = t >> 5;
    const int wm = w >> 1, wn = w & 1;     // 4 x 2 warp grid
    const int m0 = blockIdx.y * 256, n0 = blockIdx.x * 128;

    float acc[4][8][4] = {};

    auto load_stage = [&](int kt, int stage) {
        const int k0 = kt * 32;
        const uint32_t s0 = sb + stage * (QSTG * 4);
        // A: 256 rows x 32 k; thread t owns row t, 8 chunks of 16B
        const float* srcA = g_x + (size_t)(m0 + t) * DIM + k0;
        const uint32_t aBase = s0 + t * QAST * 4;
        #pragma unroll
        for (int ch = 0; ch < 8; ch++)
            CP_ASYNC16(aBase + ch * 16, srcA + ch * 4);
        // B: 32 rows x 128 n; row = t>>3, chunks (t&7)+8*it (it<4)
        const int br = t >> 3;
        const float* srcB = g_wt + (size_t)(k0 + br) * NCAT + n0;
        const uint32_t bBase = s0 + (QSTG_A + br * QBST) * 4;
        #pragma unroll
        for (int it = 0; it < 4; it++) {
            int ch = (t & 7) + it * 8;
            CP_ASYNC16(bBase + ch * 16, srcB + ch * 4);
        }
        CP_COMMIT();
    };

    auto compute_stage = [&](int stage) {
        const float* As = sm + stage * QSTG;        // [m][k] stride 36
        const float* Bs = As + QSTG_A;              // [k][n] stride 136
        #pragma unroll
        for (int ks = 0; ks < 4; ks++) {
            const int kk = ks * 8;
            uint32_t a[4][4], b[8][2];
            #pragma unroll
            for (int mt = 0; mt < 4; mt++) {
                int mb = wm * 64 + mt * 16 + (l >> 2);
                a[mt][0] = __float_as_uint(As[(size_t)mb * QAST + kk + (l & 3)]);
                a[mt][1] = __float_as_uint(As[(size_t)(mb + 8) * QAST + kk + (l & 3)]);
                a[mt][2] = __float_as_uint(As[(size_t)mb * QAST + kk + 4 + (l & 3)]);
                a[mt][3] = __float_as_uint(As[(size_t)(mb + 8) * QAST + kk + 4 + (l & 3)]);
            }
            #pragma unroll
            for (int nt = 0; nt < 8; nt++) {
                int nb = wn * 64 + nt * 8 + (l >> 2);
                b[nt][0] = __float_as_uint(Bs[(size_t)(kk + (l & 3)) * QBST + nb]);
                b[nt][1] = __float_as_uint(Bs[(size_t)(kk + 4 + (l & 3)) * QBST + nb]);
            }
            #pragma unroll
            for (int mt = 0; mt < 4; mt++)
                #pragma unroll
                for (int nt = 0; nt < 8; nt++)
                    mma8(acc[mt][nt], a[mt], b[nt]);
        }
    };

    load_stage(0, 0);
    load_stage(1, 1);
    for (int kt = 0; kt < QN_KTILE; kt++) {
        if (kt == QN_KTILE - 1) { CP_WAIT(0); } else { CP_WAIT(1); }
        __syncthreads();
        compute_stage(kt % 3);
        if (kt + 2 < QN_KTILE) load_stage(kt + 2, (kt + 2) % 3);
    }

    // epilogue by n-segment
    const int type = n0 >> 9;                 // 0:q 1:k 2:v (BN=128 divides 512)
    float* dst = (type == 0) ? g_sig : (type == 1) ? g_kw : g_v;
    const int nl0 = n0 - type * 512;

    #pragma unroll
    for (int mt = 0; mt < 4; mt++) {
        #pragma unroll
        for (int nt = 0; nt < 8; nt++) {
            int row = m0 + wm * 64 + mt * 16 + (l >> 2);
            int col = nl0 + wn * 64 + nt * 8 + 2 * (l & 3);
            float c0 = acc[mt][nt][0], c1 = acc[mt][nt][1];
            float c2 = acc[mt][nt][2], c3 = acc[mt][nt][3];
            if (type == 0) {
                c0 = 1.0f / (1.0f + __expf(-c0));
                c1 = 1.0f / (1.0f + __expf(-c1));
                c2 = 1.0f / (1.0f + __expf(-c2));
                c3 = 1.0f / (1.0f + __expf(-c3));
            } else if (type == 1) {
                c0 = __expf(c0); c1 = __expf(c1);
                c2 = __expf(c2); c3 = __expf(c3);
            }
            *(float2*)&dst[(size_t)row * DIM + col]       = make_float2(c0, c1);
            *(float2*)&dst[(size_t)(row + 8) * DIM + col] = make_float2(c2, c3);
        }
    }
}

// ---------------------------------------------------------------------------
// Attention dual-GEMM (tf32 mma.sync, 3-stage cp.async, one sync/tile)
//   acc1[j,d] += dw[i,j]*kwv[i,d] ; acc2[j,d] += dw[i,j]*kw[i,d]
// BM=128 (j), BN=64 (d), BK=32 (i); 4 warps, warp tile 64x32 dual-acc.
// grid (8, 16, 8).
// ---------------------------------------------------------------------------
#define AST 136
#define BST 72
#define STG_A (32 * AST)                   // 4352 floats
#define STG_B (32 * BST)                   // 2304 floats
#define STG   (STG_A + 2 * STG_B)          // 8960 floats
#define ATTN_SMEM (3 * STG * 4)            // 107520 bytes
#define N_ITILE (SEQ / 32)                 // 64

__global__ void __launch_bounds__(128)
attn_kernel(float* __restrict__ out) {
    extern __shared__ float sm[];
    const uint32_t sb = smem_u32(sm);
    const int t = threadIdx.x, l = t & 31, w = t >> 5;
    const int wm = w >> 1, wn = w & 1;
    const int b = blockIdx.z, j0 = blockIdx.y * 128, d0 = blockIdx.x * 64;

    const float* dwb = g_dw + (size_t)b * SEQ * SEQ;   // [i][j]
    const float* kwb = g_kw + (size_t)b * SEQ * DIM;   // [i][d]  tf32(kw)
    const float* kvb = g_v  + (size_t)b * SEQ * DIM;   // [i][d]  tf32(kw*v)

    const int lr = t >> 2;          // 0..31 (i row)
    const int lc = t & 3;           // chunk phase
    const float* srcA  = dwb + (size_t)lr * SEQ + j0;
    const float* srcB1 = kvb + (size_t)lr * DIM + d0;
    const float* srcB2 = kwb + (size_t)lr * DIM + d0;

    float acc1[4][4][4] = {};
    float acc2[4][4][4] = {};

    auto load_stage = [&](int tile, int stage) {
        const size_t iofs = (size_t)tile * 32;
        const uint32_t s0 = sb + stage * (STG * 4);
        const uint32_t aBase  = s0 + (lr * AST) * 4;
        const uint32_t b1Base = s0 + (STG_A + lr * BST) * 4;
        const uint32_t b2Base = s0 + (STG_A + STG_B + lr * BST) * 4;
        #pragma unroll
        for (int it = 0; it < 8; it++) {        // A: 32 chunks/row, 4 thr/row
            int ch = lc + it * 4;
            CP_ASYNC16(aBase + ch * 16, srcA + iofs * SEQ + ch * 4);
        }
        #pragma unroll
        for (int it = 0; it < 4; it++) {        // B: 16 chunks/row
            int ch = lc + it * 4;
            CP_ASYNC16(b1Base + ch * 16, srcB1 + iofs * DIM + ch * 4);
            CP_ASYNC16(b2Base + ch * 16, srcB2 + iofs * DIM + ch * 4);
        }
        CP_COMMIT();
    };

    auto compute_stage = [&](int stage) {
        const float* As = sm + stage * STG;     // [i][j] stride 136
        const float* B1 = As + STG_A;           // [i][d] stride 72
        const float* B2 = B1 + STG_B;
        #pragma unroll
        for (int ks = 0; ks < 4; ks++) {
            const int kk = ks * 8;
            uint32_t a[4][4], b1[4][2], b2[4][2];
            const int k0r = (kk + (l & 3)) * AST;
            const int k4r = (kk + 4 + (l & 3)) * AST;
            #pragma unroll
            for (int mt = 0; mt < 4; mt++) {
                int mb = wm * 64 + mt * 16 + (l >> 2);
                a[mt][0] = __float_as_uint(As[k0r + mb]);
                a[mt][1] = __float_as_uint(As[k0r + mb + 8]);
                a[mt][2] = __float_as_uint(As[k4r + mb]);
                a[mt][3] = __float_as_uint(As[k4r + mb + 8]);
            }
            const int k0b = (kk + (l & 3)) * BST;
            const int k4b = (kk + 4 + (l & 3)) * BST;
            #pragma unroll
            for (int nt = 0; nt < 4; nt++) {
                int nb = wn * 32 + nt * 8 + (l >> 2);
                b1[nt][0] = __float_as_uint(B1[k0b + nb]);
                b1[nt][1] = __float_as_uint(B1[k4b + nb]);
                b2[nt][0] = __float_as_uint(B2[k0b + nb]);
                b2[nt][1] = __float_as_uint(B2[k4b + nb]);
            }
            #pragma unroll
            for (int mt = 0; mt < 4; mt++) {
                #pragma unroll
                for (int nt = 0; nt < 4; nt++) {
                    mma8(acc1[mt][nt], a[mt], b1[nt]);
                    mma8(acc2[mt][nt], a[mt], b2[nt]);
                }
            }
        }
    };

    load_stage(0, 0);
    load_stage(1, 1);
    for (int tile = 0; tile < N_ITILE; tile++) {
        if (tile == N_ITILE - 1) { CP_WAIT(0); } else { CP_WAIT(1); }
        __syncthreads();
        compute_stage(tile % 3);
        if (tile + 2 < N_ITILE) load_stage(tile + 2, (tile + 2) % 3);
    }

    // epilogue: out = sig * acc1/acc2
    const float* sigb = g_sig + (size_t)b * SEQ * DIM;
    float* outb = out + (size_t)b * SEQ * DIM;
    #pragma unroll
    for (int mt = 0; mt < 4; mt++) {
        #pragma unroll
        for (int nt = 0; nt < 4; nt++) {
            int jr = j0 + wm * 64 + mt * 16 + (l >> 2);
            int dc = d0 + wn * 32 + nt * 8 + 2 * (l & 3);
            size_t i0x = (size_t)jr * DIM + dc;
            size_t i1x = (size_t)(jr + 8) * DIM + dc;
            float2 s0 = *(const float2*)&sigb[i0x];
            float2 s1 = *(const float2*)&sigb[i1x];
            float2 o0, o1;
            o0.x = s0.x * __fdividef(acc1[mt][nt][0], acc2[mt][nt][0]);
            o0.y = s0.y * __fdividef(acc1[mt][nt][1], acc2[mt][nt][1]);
            o1.x = s1.x * __fdividef(acc1[mt][nt][2], acc2[mt][nt][2]);
            o1.y = s1.y * __fdividef(acc1[mt][nt][3], acc2[mt][nt][3]);
            *(float2*)&outb[i0x] = o0;
            *(float2*)&outb[i1x] = o1;
        }
    }
}

// ---------------------------------------------------------------------------
// Launch
// ---------------------------------------------------------------------------
extern "C" void kernel_launch(void* const* d_in, const int* in_sizes, int n_in,
                              void* d_out, int out_size) {
    const float* x     = (const float*)d_in[0];
    const float* dis   = (const float*)d_in[1];
    const float* Wq    = (const float*)d_in[2];
    const float* Wk    = (const float*)d_in[3];
    const float* Wv    = (const float*)d_in[4];
    const float* alpha = (const float*)d_in[5];
    float* out = (float*)d_out;

    cudaFuncSetAttribute(attn_kernel, cudaFuncAttributeMaxDynamicSharedMemorySize, ATTN_SMEM);
    cudaFuncSetAttribute(qkv_kernel,  cudaFuncAttributeMaxDynamicSharedMemorySize, QKV_SMEM);

    {   // weights transpose+concat (tf32)
        dim3 grid(DIM / 32, DIM / 32, 3), block(32, 8);
        transpose_w_kernel<<<grid, block>>>(Wq, Wk, Wv);
    }
    {   // x pre-round
        xr_kernel<<<8192, 256>>>(x);
    }
    {   // dw precompute
        dw_kernel<<<32768, 256>>>(dis, alpha);
    }
    {   // pipelined QKV projection (256 thr, BM=256)
        dim3 grid(NCAT / 128, M_TOT / 256), block(256);
        qkv_kernel<<<grid, block, QKV_SMEM>>>();
    }
    {   // fold kw*v + tf32 rounding
        fold_kernel<<<8192, 256>>>();
    }
    {   // pipelined dual-GEMM attention
        dim3 grid(DIM / 64, SEQ / 128, BATCH), block(128);
        attn_kernel<<<grid, block, ATTN_SMEM>>>(out);
    }
}

// round 10
// speedup vs baseline: 4.6337x; 1.3612x over previous
#include <cuda_runtime.h>
#include <cuda_fp16.h>
#include <math.h>
#include <stdint.h>

#define BATCH 8
#define SEQ   2048
#define DIM   512
#define M_TOT (BATCH * SEQ)   // 16384
#define NCAT  (3 * DIM)       // 1536

// Scratch (device globals)
__device__ float  g_sig [M_TOT * DIM];                 // sigmoid(q) f32
__device__ float  g_kw  [M_TOT * DIM];                 // exp(k) f32 [i][d]
__device__ float  g_v   [M_TOT * DIM];                 // v f32 [i][d]
__device__ __half g_xh  [M_TOT * DIM];                 // fp16(x) [m][k]
__device__ __half g_wh  [NCAT * DIM];                  // fp16 W concat [n][k] (no transpose)
__device__ __half g_dwh [(size_t)BATCH * SEQ * SEQ];   // fp16(exp(coef*dis)) [b][j][i]
__device__ __half g_kwh [(size_t)BATCH * DIM * SEQ];   // fp16(kw)    [b][d][i]
__device__ __half g_kwvh[(size_t)BATCH * DIM * SEQ];   // fp16(kw*v)  [b][d][i]

// ---------------------------------------------------------------------------
// helpers
// ---------------------------------------------------------------------------
__device__ __forceinline__ uint32_t smem_u32(const void* p) {
    uint32_t a;
    asm("{ .reg .u64 t; cvta.to.shared.u64 t, %1; cvt.u32.u64 %0, t; }" : "=r"(a) : "l"(p));
    return a;
}

#define CP_ASYNC16(dst, src) \
    asm volatile("cp.async.cg.shared.global [%0], [%1], 16;" :: "r"(dst), "l"(src))
#define CP_COMMIT() asm volatile("cp.async.commit_group;" ::: "memory")
#define CP_WAIT(n)  asm volatile("cp.async.wait_group %0;" :: "n"(n) : "memory")

// fp16 m16n8k16: a = 4 x .b32 (8 halves), b = 2 x .b32 (4 halves), c = 4 x f32
__device__ __forceinline__ void mma16(float* c, const uint32_t* a, const uint32_t* b) {
    asm volatile(
        "mma.sync.aligned.m16n8k16.row.col.f32.f16.f16.f32 "
        "{%0,%1,%2,%3},{%4,%5,%6,%7},{%8,%9},{%0,%1,%2,%3};"
        : "+f"(c[0]), "+f"(c[1]), "+f"(c[2]), "+f"(c[3])
        : "r"(a[0]), "r"(a[1]), "r"(a[2]), "r"(a[3]), "r"(b[0]), "r"(b[1]));
}

// ---------------------------------------------------------------------------
// Weight convert+concat (NO transpose): g_wh[z*512 + n][k] = fp16(W_z[n][k])
// grid (256, 3), block 256; 4 elems/thread
// ---------------------------------------------------------------------------
__global__ void wconv_kernel(const float* __restrict__ Wq,
                             const float* __restrict__ Wk,
                             const float* __restrict__ Wv) {
    const float* W = (blockIdx.y == 0) ? Wq : (blockIdx.y == 1) ? Wk : Wv;
    int i = (blockIdx.x * 256 + threadIdx.x) * 4;
    float4 v = *(const float4*)&W[i];
    __half* dst = g_wh + (size_t)blockIdx.y * DIM * DIM + i;
    *(__half2*)&dst[0] = __floats2half2_rn(v.x, v.y);
    *(__half2*)&dst[2] = __floats2half2_rn(v.z, v.w);
}

// ---------------------------------------------------------------------------
// x convert: g_xh = fp16(x)
// ---------------------------------------------------------------------------
__global__ void xh_kernel(const float* __restrict__ x) {
    size_t i = ((size_t)blockIdx.x * blockDim.x + threadIdx.x) * 4;
    float4 v = *(const float4*)(x + i);
    *(__half2*)&g_xh[i]     = __floats2half2_rn(v.x, v.y);
    *(__half2*)&g_xh[i + 2] = __floats2half2_rn(v.z, v.w);
}

// ---------------------------------------------------------------------------
// dwt: g_dwh[b][j][i] = fp16(exp(coef * dis[b][i][j]))  (transpose + exp)
// grid (64, 64, 8), block (32, 8)
// ---------------------------------------------------------------------------
__global__ void dwt_kernel(const float* __restrict__ dis,
                           const float* __restrict__ alpha_p) {
    __shared__ float tile[32][33];
    const float coef = -(alpha_p[0] * 11.0f);   // -alpha*log2(2048)
    const float* db = dis + (size_t)blockIdx.z * SEQ * SEQ;
    __half* ob = g_dwh + (size_t)blockIdx.z * SEQ * SEQ;
    int j = blockIdx.x * 32 + threadIdx.x;
    int i = blockIdx.y * 32 + threadIdx.y;
    #pragma unroll
    for (int r = 0; r < 32; r += 8)
        tile[threadIdx.y + r][threadIdx.x] = __expf(coef * db[(size_t)(i + r) * SEQ + j]);
    __syncthreads();
    int io = blockIdx.y * 32 + threadIdx.x;
    int jo = blockIdx.x * 32 + threadIdx.y;
    #pragma unroll
    for (int r = 0; r < 32; r += 8)
        ob[(size_t)(jo + r) * SEQ + io] = __float2half_rn(tile[threadIdx.x][threadIdx.y + r]);
}

// ---------------------------------------------------------------------------
// kvt: g_kwh[b][d][i] = fp16(kw); g_kwvh[b][d][i] = fp16(kw*v)  (transpose)
// grid (16, 64, 8), block (32, 8)
// ---------------------------------------------------------------------------
__global__ void kvt_kernel() {
    __shared__ float t1[32][33];   // kw*v
    __shared__ float t2[32][33];   // kw
    const float* kwb = g_kw + (size_t)blockIdx.z * SEQ * DIM;
    const float* vb  = g_v  + (size_t)blockIdx.z * SEQ * DIM;
    __half* o1 = g_kwvh + (size_t)blockIdx.z * DIM * SEQ;
    __half* o2 = g_kwh  + (size_t)blockIdx.z * DIM * SEQ;
    int d = blockIdx.x * 32 + threadIdx.x;
    int i = blockIdx.y * 32 + threadIdx.y;
    #pragma unroll
    for (int r = 0; r < 32; r += 8) {
        float kw = kwb[(size_t)(i + r) * DIM + d];
        float vv = vb [(size_t)(i + r) * DIM + d];
        t2[threadIdx.y + r][threadIdx.x] = kw;
        t1[threadIdx.y + r][threadIdx.x] = kw * vv;
    }
    __syncthreads();
    int io = blockIdx.y * 32 + threadIdx.x;
    int do_ = blockIdx.x * 32 + threadIdx.y;
    #pragma unroll
    for (int r = 0; r < 32; r += 8) {
        o1[(size_t)(do_ + r) * SEQ + io] = __float2half_rn(t1[threadIdx.x][threadIdx.y + r]);
        o2[(size_t)(do_ + r) * SEQ + io] = __float2half_rn(t2[threadIdx.x][threadIdx.y + r]);
    }
}

// ---------------------------------------------------------------------------
// QKV GEMM (fp16 m16n8k16): C[m,n] = sum_k xh[m,k] * wh[n,k]
// M=16384, N=1536, K=512. BM=128, BN=128, BK=32, 128 thr (4 warps 2x2),
// warp tile 64x64, 3-stage cp.async, 1 sync/tile. grid (12, 128), 3 CTAs/SM.
// ---------------------------------------------------------------------------
#define QASTH 40                           // halves per row (32 + 8 pad)
#define QA_BYTES (128 * QASTH * 2)         // 10240
#define QSTG_BYTES (2 * QA_BYTES)          // 20480 (A + B, both 128 rows)
#define QKV_SMEM (3 * QSTG_BYTES)          // 61440
#define QN_KTILE (DIM / 32)                // 16

__global__ void __launch_bounds__(128, 3)
qkv_kernel() {
    extern __shared__ char smc[];
    const uint32_t sb = smem_u32(smc);
    const int t = threadIdx.x, l = t & 31, w = t >> 5;
    const int wm = w >> 1, wn = w & 1;
    const int m0 = blockIdx.y * 128, n0 = blockIdx.x * 128;

    float acc[4][8][4] = {};

    auto load_stage = [&](int kt, int stage) {
        const int k0 = kt * 32;
        const uint32_t s0 = sb + stage * QSTG_BYTES;
        // A: 128 rows x 32 k halves (64B/row); thread t owns row t, 4 chunks
        const __half* srcA = g_xh + (size_t)(m0 + t) * DIM + k0;
        const uint32_t aBase = s0 + t * (QASTH * 2);
        #pragma unroll
        for (int ch = 0; ch < 4; ch++)
            CP_ASYNC16(aBase + ch * 16, srcA + ch * 8);
        // B: 128 rows (n) x 32 k halves; thread t owns row t
        const __half* srcB = g_wh + (size_t)(n0 + t) * DIM + k0;
        const uint32_t bBase = s0 + QA_BYTES + t * (QASTH * 2);
        #pragma unroll
        for (int ch = 0; ch < 4; ch++)
            CP_ASYNC16(bBase + ch * 16, srcB + ch * 8);
        CP_COMMIT();
    };

    auto compute_stage = [&](int stage) {
        const __half* As = (const __half*)(smc + stage * QSTG_BYTES);   // [m][k] stride 40
        const __half* Bs = As + 128 * QASTH;                            // [n][k] stride 40
        #pragma unroll
        for (int ks = 0; ks < 2; ks++) {
            const int kk = ks * 16;
            uint32_t a[4][4], b[8][2];
            #pragma unroll
            for (int mt = 0; mt < 4; mt++) {
                int mb = wm * 64 + mt * 16 + (l >> 2);
                const __half* r0 = &As[(size_t)mb * QASTH + kk + 2 * (l & 3)];
                const __half* r1 = &As[(size_t)(mb + 8) * QASTH + kk + 2 * (l & 3)];
                a[mt][0] = *(const uint32_t*)r0;
                a[mt][1] = *(const uint32_t*)r1;
                a[mt][2] = *(const uint32_t*)(r0 + 8);
                a[mt][3] = *(const uint32_t*)(r1 + 8);
            }
            #pragma unroll
            for (int nt = 0; nt < 8; nt++) {
                int nb = wn * 64 + nt * 8 + (l >> 2);
                const __half* rb = &Bs[(size_t)nb * QASTH + kk + 2 * (l & 3)];
                b[nt][0] = *(const uint32_t*)rb;
                b[nt][1] = *(const uint32_t*)(rb + 8);
            }
            #pragma unroll
            for (int mt = 0; mt < 4; mt++)
                #pragma unroll
                for (int nt = 0; nt < 8; nt++)
                    mma16(acc[mt][nt], a[mt], b[nt]);
        }
    };

    load_stage(0, 0);
    load_stage(1, 1);
    for (int kt = 0; kt < QN_KTILE; kt++) {
        if (kt == QN_KTILE - 1) { CP_WAIT(0); } else { CP_WAIT(1); }
        __syncthreads();
        compute_stage(kt % 3);
        if (kt + 2 < QN_KTILE) load_stage(kt + 2, (kt + 2) % 3);
    }

    // epilogue by n-segment
    const int type = n0 >> 9;                 // 0:q 1:k 2:v
    float* dst = (type == 0) ? g_sig : (type == 1) ? g_kw : g_v;
    const int nl0 = n0 - type * 512;

    #pragma unroll
    for (int mt = 0; mt < 4; mt++) {
        #pragma unroll
        for (int nt = 0; nt < 8; nt++) {
            int row = m0 + wm * 64 + mt * 16 + (l >> 2);
            int col = nl0 + wn * 64 + nt * 8 + 2 * (l & 3);
            float c0 = acc[mt][nt][0], c1 = acc[mt][nt][1];
            float c2 = acc[mt][nt][2], c3 = acc[mt][nt][3];
            if (type == 0) {
                c0 = 1.0f / (1.0f + __expf(-c0));
                c1 = 1.0f / (1.0f + __expf(-c1));
                c2 = 1.0f / (1.0f + __expf(-c2));
                c3 = 1.0f / (1.0f + __expf(-c3));
            } else if (type == 1) {
                c0 = __expf(c0); c1 = __expf(c1);
                c2 = __expf(c2); c3 = __expf(c3);
            }
            *(float2*)&dst[(size_t)row * DIM + col]       = make_float2(c0, c1);
            *(float2*)&dst[(size_t)(row + 8) * DIM + col] = make_float2(c2, c3);
        }
    }
}

// ---------------------------------------------------------------------------
// Attention dual-GEMM (fp16 m16n8k16, 3-stage, 1 sync/tile)
//   acc1[j,d] += dw[j,i]*kwv[d,i] ; acc2[j,d] += dw[j,i]*kw[d,i]   (contract i)
// BM=128 (j), BN=64 (d), BK=32 (i); 128 thr (4 warps 2x2), warp tile 64x32
// dual acc. grid (8, 16, 8), 3 CTAs/SM.
// ---------------------------------------------------------------------------
#define ASTH 40
#define AA_BYTES (128 * ASTH * 2)          // 10240
#define AB_BYTES (64 * ASTH * 2)           // 5120
#define ASTG_BYTES (AA_BYTES + 2 * AB_BYTES)   // 20480
#define ATTN_SMEM (3 * ASTG_BYTES)         // 61440
#define N_ITILE (SEQ / 32)                 // 64

__global__ void __launch_bounds__(128, 3)
attn_kernel(float* __restrict__ out) {
    extern __shared__ char smc[];
    const uint32_t sb = smem_u32(smc);
    const int t = threadIdx.x, l = t & 31, w = t >> 5;
    const int wm = w >> 1, wn = w & 1;
    const int b = blockIdx.z, j0 = blockIdx.y * 128, d0 = blockIdx.x * 64;

    const __half* dwb = g_dwh  + (size_t)b * SEQ * SEQ;   // [j][i]
    const __half* kvb = g_kwvh + (size_t)b * DIM * SEQ;   // [d][i]
    const __half* kwb = g_kwh  + (size_t)b * DIM * SEQ;   // [d][i]

    const __half* srcA  = dwb + (size_t)(j0 + t) * SEQ;          // row j0+t
    const __half* srcB1 = kvb + (size_t)(d0 + (t >> 1)) * SEQ;   // row d0+(t>>1)
    const __half* srcB2 = kwb + (size_t)(d0 + (t >> 1)) * SEQ;

    float acc1[4][4][4] = {};
    float acc2[4][4][4] = {};

    auto load_stage = [&](int tile, int stage) {
        const int i0 = tile * 32;
        const uint32_t s0 = sb + stage * ASTG_BYTES;
        // A: 128 rows x 32 i halves; thread t owns row t, 4 chunks
        const uint32_t aBase = s0 + t * (ASTH * 2);
        #pragma unroll
        for (int ch = 0; ch < 4; ch++)
            CP_ASYNC16(aBase + ch * 16, srcA + i0 + ch * 8);
        // B1/B2: 64 rows x 32 i halves; 2 threads/row, 2 chunks each
        const int bch = 2 * (t & 1);
        const uint32_t b1Base = s0 + AA_BYTES + (t >> 1) * (ASTH * 2);
        const uint32_t b2Base = b1Base + AB_BYTES;
        CP_ASYNC16(b1Base + bch * 16,        srcB1 + i0 + bch * 8);
        CP_ASYNC16(b1Base + (bch + 1) * 16,  srcB1 + i0 + (bch + 1) * 8);
        CP_ASYNC16(b2Base + bch * 16,        srcB2 + i0 + bch * 8);
        CP_ASYNC16(b2Base + (bch + 1) * 16,  srcB2 + i0 + (bch + 1) * 8);
        CP_COMMIT();
    };

    auto compute_stage = [&](int stage) {
        const __half* As = (const __half*)(smc + stage * ASTG_BYTES);  // [j][i] stride 40
        const __half* B1 = As + 128 * ASTH;                            // [d][i] stride 40
        const __half* B2 = B1 + 64 * ASTH;
        #pragma unroll
        for (int ks = 0; ks < 2; ks++) {
            const int kk = ks * 16;
            uint32_t a[4][4], b1[4][2], b2[4][2];
            #pragma unroll
            for (int mt = 0; mt < 4; mt++) {
                int mb = wm * 64 + mt * 16 + (l >> 2);
                const __half* r0 = &As[(size_t)mb * ASTH + kk + 2 * (l & 3)];
                const __half* r1 = &As[(size_t)(mb + 8) * ASTH + kk + 2 * (l & 3)];
                a[mt][0] = *(const uint32_t*)r0;
                a[mt][1] = *(const uint32_t*)r1;
                a[mt][2] = *(const uint32_t*)(r0 + 8);
                a[mt][3] = *(const uint32_t*)(r1 + 8);
            }
            #pragma unroll
            for (int nt = 0; nt < 4; nt++) {
                int nb = wn * 32 + nt * 8 + (l >> 2);
                const __half* p1 = &B1[(size_t)nb * ASTH + kk + 2 * (l & 3)];
                const __half* p2 = &B2[(size_t)nb * ASTH + kk + 2 * (l & 3)];
                b1[nt][0] = *(const uint32_t*)p1;
                b1[nt][1] = *(const uint32_t*)(p1 + 8);
                b2[nt][0] = *(const uint32_t*)p2;
                b2[nt][1] = *(const uint32_t*)(p2 + 8);
            }
            #pragma unroll
            for (int mt = 0; mt < 4; mt++) {
                #pragma unroll
                for (int nt = 0; nt < 4; nt++) {
                    mma16(acc1[mt][nt], a[mt], b1[nt]);
                    mma16(acc2[mt][nt], a[mt], b2[nt]);
                }
            }
        }
    };

    load_stage(0, 0);
    load_stage(1, 1);
    for (int tile = 0; tile < N_ITILE; tile++) {
        if (tile == N_ITILE - 1) { CP_WAIT(0); } else { CP_WAIT(1); }
        __syncthreads();
        compute_stage(tile % 3);
        if (tile + 2 < N_ITILE) load_stage(tile + 2, (tile + 2) % 3);
    }

    // epilogue: out = sig * acc1/acc2
    const float* sigb = g_sig + (size_t)b * SEQ * DIM;
    float* outb = out + (size_t)b * SEQ * DIM;
    #pragma unroll
    for (int mt = 0; mt < 4; mt++) {
        #pragma unroll
        for (int nt = 0; nt < 4; nt++) {
            int jr = j0 + wm * 64 + mt * 16 + (l >> 2);
            int dc = d0 + wn * 32 + nt * 8 + 2 * (l & 3);
            size_t i0x = (size_t)jr * DIM + dc;
            size_t i1x = (size_t)(jr + 8) * DIM + dc;
            float2 s0 = *(const float2*)&sigb[i0x];
            float2 s1 = *(const float2*)&sigb[i1x];
            float2 o0, o1;
            o0.x = s0.x * __fdividef(acc1[mt][nt][0], acc2[mt][nt][0]);
            o0.y = s0.y * __fdividef(acc1[mt][nt][1], acc2[mt][nt][1]);
            o1.x = s1.x * __fdividef(acc1[mt][nt][2], acc2[mt][nt][2]);
            o1.y = s1.y * __fdividef(acc1[mt][nt][3], acc2[mt][nt][3]);
            *(float2*)&outb[i0x] = o0;
            *(float2*)&outb[i1x] = o1;
        }
    }
}

// ---------------------------------------------------------------------------
// Launch
// ---------------------------------------------------------------------------
extern "C" void kernel_launch(void* const* d_in, const int* in_sizes, int n_in,
                              void* d_out, int out_size) {
    const float* x     = (const float*)d_in[0];
    const float* dis   = (const float*)d_in[1];
    const float* Wq    = (const float*)d_in[2];
    const float* Wk    = (const float*)d_in[3];
    const float* Wv    = (const float*)d_in[4];
    const float* alpha = (const float*)d_in[5];
    float* out = (float*)d_out;

    cudaFuncSetAttribute(attn_kernel, cudaFuncAttributeMaxDynamicSharedMemorySize, ATTN_SMEM);
    cudaFuncSetAttribute(qkv_kernel,  cudaFuncAttributeMaxDynamicSharedMemorySize, QKV_SMEM);

    {   // weight convert+concat (fp16, [n][k])
        dim3 grid(256, 3), block(256);
        wconv_kernel<<<grid, block>>>(Wq, Wk, Wv);
    }
    {   // x convert
        xh_kernel<<<8192, 256>>>(x);
    }
    {   // dw = fp16(exp(coef*dis)) transposed [b][j][i]
        dim3 grid(SEQ / 32, SEQ / 32, BATCH), block(32, 8);
        dwt_kernel<<<grid, block>>>(dis, alpha);
    }
    {   // fp16 QKV projection
        dim3 grid(NCAT / 128, M_TOT / 128), block(128);
        qkv_kernel<<<grid, block, QKV_SMEM>>>();
    }
    {   // kw / kw*v transpose to fp16 [b][d][i]
        dim3 grid(DIM / 32, SEQ / 32, BATCH), block(32, 8);
        kvt_kernel<<<grid, block>>>();
    }
    {   // fp16 dual-GEMM attention
        dim3 grid(DIM / 64, SEQ / 128, BATCH), block(128);
        attn_kernel<<<grid, block, ATTN_SMEM>>>(out);
    }
}

// round 13
// speedup vs baseline: 4.6874x; 1.0116x over previous
#include <cuda_runtime.h>
#include <cuda_fp16.h>
#include <math.h>
#include <stdint.h>

#define BATCH 8
#define SEQ   2048
#define DIM   512
#define M_TOT (BATCH * SEQ)   // 16384
#define NCAT  (3 * DIM)       // 1536

// Scratch (device globals)
__device__ float  g_sig [M_TOT * DIM];                 // sigmoid(q) f32
__device__ float  g_kw  [M_TOT * DIM];                 // exp(k) f32 [i][d]
__device__ float  g_v   [M_TOT * DIM];                 // v f32 [i][d]
__device__ __half g_xh  [M_TOT * DIM];                 // fp16(x) [m][k]
__device__ __half g_wh  [NCAT * DIM];                  // fp16 W concat [n][k]
__device__ __half g_dwh [(size_t)BATCH * SEQ * SEQ];   // fp16(exp(coef*dis)) [b][j][i]
__device__ __half g_kwh [(size_t)BATCH * DIM * SEQ];   // fp16(kw)    [b][d][i]
__device__ __half g_kwvh[(size_t)BATCH * DIM * SEQ];   // fp16(kw*v)  [b][d][i]

// ---------------------------------------------------------------------------
// helpers
// ---------------------------------------------------------------------------
__device__ __forceinline__ uint32_t smem_u32(const void* p) {
    uint32_t a;
    asm("{ .reg .u64 t; cvta.to.shared.u64 t, %1; cvt.u32.u64 %0, t; }" : "=r"(a) : "l"(p));
    return a;
}

#define CP_ASYNC16(dst, src) \
    asm volatile("cp.async.cg.shared.global [%0], [%1], 16;" :: "r"(dst), "l"(src))
#define CP_COMMIT() asm volatile("cp.async.commit_group;" ::: "memory")
#define CP_WAIT(n)  asm volatile("cp.async.wait_group %0;" :: "n"(n) : "memory")

// fp16 m16n8k16
__device__ __forceinline__ void mma16(float* c, const uint32_t* a, const uint32_t* b) {
    asm volatile(
        "mma.sync.aligned.m16n8k16.row.col.f32.f16.f16.f32 "
        "{%0,%1,%2,%3},{%4,%5,%6,%7},{%8,%9},{%0,%1,%2,%3};"
        : "+f"(c[0]), "+f"(c[1]), "+f"(c[2]), "+f"(c[3])
        : "r"(a[0]), "r"(a[1]), "r"(a[2]), "r"(a[3]), "r"(b[0]), "r"(b[1]));
}

__device__ __forceinline__ void ldsm_x4(uint32_t* r, uint32_t addr) {
    asm volatile("ldmatrix.sync.aligned.m8n8.x4.shared.b16 {%0,%1,%2,%3}, [%4];"
        : "=r"(r[0]), "=r"(r[1]), "=r"(r[2]), "=r"(r[3]) : "r"(addr));
}

// ---------------------------------------------------------------------------
// Weight convert+concat (NO transpose): g_wh[z*512 + n][k] = fp16(W_z[n][k])
// ---------------------------------------------------------------------------
__global__ void wconv_kernel(const float* __restrict__ Wq,
                             const float* __restrict__ Wk,
                             const float* __restrict__ Wv) {
    const float* W = (blockIdx.y == 0) ? Wq : (blockIdx.y == 1) ? Wk : Wv;
    int i = (blockIdx.x * 256 + threadIdx.x) * 4;
    float4 v = *(const float4*)&W[i];
    __half* dst = g_wh + (size_t)blockIdx.y * DIM * DIM + i;
    *(__half2*)&dst[0] = __floats2half2_rn(v.x, v.y);
    *(__half2*)&dst[2] = __floats2half2_rn(v.z, v.w);
}

// ---------------------------------------------------------------------------
// x convert: g_xh = fp16(x)
// ---------------------------------------------------------------------------
__global__ void xh_kernel(const float* __restrict__ x) {
    size_t i = ((size_t)blockIdx.x * blockDim.x + threadIdx.x) * 4;
    float4 v = *(const float4*)(x + i);
    *(__half2*)&g_xh[i]     = __floats2half2_rn(v.x, v.y);
    *(__half2*)&g_xh[i + 2] = __floats2half2_rn(v.z, v.w);
}

// ---------------------------------------------------------------------------
// dwt: g_dwh[b][j][i] = fp16(exp(coef * dis[b][i][j]))  (transpose + exp)
// ---------------------------------------------------------------------------
__global__ void dwt_kernel(const float* __restrict__ dis,
                           const float* __restrict__ alpha_p) {
    __shared__ float tile[32][33];
    const float coef = -(alpha_p[0] * 11.0f);   // -alpha*log2(2048)
    const float* db = dis + (size_t)blockIdx.z * SEQ * SEQ;
    __half* ob = g_dwh + (size_t)blockIdx.z * SEQ * SEQ;
    int j = blockIdx.x * 32 + threadIdx.x;
    int i = blockIdx.y * 32 + threadIdx.y;
    #pragma unroll
    for (int r = 0; r < 32; r += 8)
        tile[threadIdx.y + r][threadIdx.x] = __expf(coef * db[(size_t)(i + r) * SEQ + j]);
    __syncthreads();
    int io = blockIdx.y * 32 + threadIdx.x;
    int jo = blockIdx.x * 32 + threadIdx.y;
    #pragma unroll
    for (int r = 0; r < 32; r += 8)
        ob[(size_t)(jo + r) * SEQ + io] = __float2half_rn(tile[threadIdx.x][threadIdx.y + r]);
}

// ---------------------------------------------------------------------------
// kvt: g_kwh[b][d][i] = fp16(kw); g_kwvh[b][d][i] = fp16(kw*v)  (transpose)
// ---------------------------------------------------------------------------
__global__ void kvt_kernel() {
    __shared__ float t1[32][33];
    __shared__ float t2[32][33];
    const float* kwb = g_kw + (size_t)blockIdx.z * SEQ * DIM;
    const float* vb  = g_v  + (size_t)blockIdx.z * SEQ * DIM;
    __half* o1 = g_kwvh + (size_t)blockIdx.z * DIM * SEQ;
    __half* o2 = g_kwh  + (size_t)blockIdx.z * DIM * SEQ;
    int d = blockIdx.x * 32 + threadIdx.x;
    int i = blockIdx.y * 32 + threadIdx.y;
    #pragma unroll
    for (int r = 0; r < 32; r += 8) {
        float kw = kwb[(size_t)(i + r) * DIM + d];
        float vv = vb [(size_t)(i + r) * DIM + d];
        t2[threadIdx.y + r][threadIdx.x] = kw;
        t1[threadIdx.y + r][threadIdx.x] = kw * vv;
    }
    __syncthreads();
    int io = blockIdx.y * 32 + threadIdx.x;
    int do_ = blockIdx.x * 32 + threadIdx.y;
    #pragma unroll
    for (int r = 0; r < 32; r += 8) {
        o1[(size_t)(do_ + r) * SEQ + io] = __float2half_rn(t1[threadIdx.x][threadIdx.y + r]);
        o2[(size_t)(do_ + r) * SEQ + io] = __float2half_rn(t2[threadIdx.x][threadIdx.y + r]);
    }
}

// ---------------------------------------------------------------------------
// QKV GEMM (fp16 m16n8k16 + ldmatrix): C[m,n] = sum_k xh[m,k] * wh[n,k]
// BM=128, BN=128, BK=32, 128 thr (4 warps 2x2), warp tile 64x64,
// 3-stage cp.async, 1 sync/tile. grid (12, 128), 3 CTAs/SM.
// ---------------------------------------------------------------------------
#define QASTH 40                           // halves per row (32 + 8 pad)
#define QA_BYTES (128 * QASTH * 2)         // 10240
#define QSTG_BYTES (2 * QA_BYTES)          // 20480
#define QKV_SMEM (3 * QSTG_BYTES)          // 61440
#define QN_KTILE (DIM / 32)                // 16

__global__ void __launch_bounds__(128, 3)
qkv_kernel() {
    extern __shared__ char smc[];
    const uint32_t sb = smem_u32(smc);
    const int t = threadIdx.x, l = t & 31, w = t >> 5;
    const int wm = w >> 1, wn = w & 1;
    const int m0 = blockIdx.y * 128, n0 = blockIdx.x * 128;

    float acc[4][8][4] = {};

    // lane-dependent ldmatrix geometry (byte offsets within a stage)
    const uint32_t aRow = wm * 64 + (l & 15);          // + mt*16
    const uint32_t aCol = 8 * (l >> 4);                // + kk
    const uint32_t bRow = wn * 64 + 8 * (l >> 4) + (l & 7);   // + np*16
    const uint32_t bCol = 8 * ((l >> 3) & 1);          // + kk
    const uint32_t aOff = (aRow * QASTH + aCol) * 2;
    const uint32_t bOff = QA_BYTES + (bRow * QASTH + bCol) * 2;

    auto load_stage = [&](int kt, int stage) {
        const int k0 = kt * 32;
        const uint32_t s0 = sb + stage * QSTG_BYTES;
        const __half* srcA = g_xh + (size_t)(m0 + t) * DIM + k0;
        const uint32_t aBase = s0 + t * (QASTH * 2);
        #pragma unroll
        for (int ch = 0; ch < 4; ch++)
            CP_ASYNC16(aBase + ch * 16, srcA + ch * 8);
        const __half* srcB = g_wh + (size_t)(n0 + t) * DIM + k0;
        const uint32_t bBase = s0 + QA_BYTES + t * (QASTH * 2);
        #pragma unroll
        for (int ch = 0; ch < 4; ch++)
            CP_ASYNC16(bBase + ch * 16, srcB + ch * 8);
        CP_COMMIT();
    };

    auto compute_stage = [&](int stage) {
        const uint32_t s0 = sb + stage * QSTG_BYTES;
        #pragma unroll
        for (int ks = 0; ks < 2; ks++) {
            const int kk = ks * 16;
            uint32_t a[4][4], b[8][2];
            #pragma unroll
            for (int mt = 0; mt < 4; mt++)
                ldsm_x4(a[mt], s0 + aOff + (mt * 16 * QASTH + kk) * 2);
            #pragma unroll
            for (int np = 0; np < 4; np++) {
                uint32_t r[4];
                ldsm_x4(r, s0 + bOff + (np * 16 * QASTH + kk) * 2);
                b[np * 2][0] = r[0]; b[np * 2][1] = r[1];
                b[np * 2 + 1][0] = r[2]; b[np * 2 + 1][1] = r[3];
            }
            #pragma unroll
            for (int mt = 0; mt < 4; mt++)
                #pragma unroll
                for (int nt = 0; nt < 8; nt++)
                    mma16(acc[mt][nt], a[mt], b[nt]);
        }
    };

    load_stage(0, 0);
    load_stage(1, 1);
    for (int kt = 0; kt < QN_KTILE; kt++) {
        if (kt == QN_KTILE - 1) { CP_WAIT(0); } else { CP_WAIT(1); }
        __syncthreads();
        compute_stage(kt % 3);
        if (kt + 2 < QN_KTILE) load_stage(kt + 2, (kt + 2) % 3);
    }

    // epilogue by n-segment
    const int type = n0 >> 9;
    float* dst = (type == 0) ? g_sig : (type == 1) ? g_kw : g_v;
    const int nl0 = n0 - type * 512;

    #pragma unroll
    for (int mt = 0; mt < 4; mt++) {
        #pragma unroll
        for (int nt = 0; nt < 8; nt++) {
            int row = m0 + wm * 64 + mt * 16 + (l >> 2);
            int col = nl0 + wn * 64 + nt * 8 + 2 * (l & 3);
            float c0 = acc[mt][nt][0], c1 = acc[mt][nt][1];
            float c2 = acc[mt][nt][2], c3 = acc[mt][nt][3];
            if (type == 0) {
                c0 = 1.0f / (1.0f + __expf(-c0));
                c1 = 1.0f / (1.0f + __expf(-c1));
                c2 = 1.0f / (1.0f + __expf(-c2));
                c3 = 1.0f / (1.0f + __expf(-c3));
            } else if (type == 1) {
                c0 = __expf(c0); c1 = __expf(c1);
                c2 = __expf(c2); c3 = __expf(c3);
            }
            *(float2*)&dst[(size_t)row * DIM + col]       = make_float2(c0, c1);
            *(float2*)&dst[(size_t)(row + 8) * DIM + col] = make_float2(c2, c3);
        }
    }
}

// ---------------------------------------------------------------------------
// Attention dual-GEMM (fp16 m16n8k16 + ldmatrix, 3-stage, 1 sync/tile)
// BM=128 (j), BN=64 (d), BK=32 (i); 128 thr (4 warps 2x2), warp tile 64x32
// dual acc. grid (8, 16, 8), 3 CTAs/SM.
// ---------------------------------------------------------------------------
#define ASTH 40
#define AA_BYTES (128 * ASTH * 2)          // 10240
#define AB_BYTES (64 * ASTH * 2)           // 5120
#define ASTG_BYTES (AA_BYTES + 2 * AB_BYTES)   // 20480
#define ATTN_SMEM (3 * ASTG_BYTES)         // 61440
#define N_ITILE (SEQ / 32)                 // 64

__global__ void __launch_bounds__(128, 3)
attn_kernel(float* __restrict__ out) {
    extern __shared__ char smc[];
    const uint32_t sb = smem_u32(smc);
    const int t = threadIdx.x, l = t & 31, w = t >> 5;
    const int wm = w >> 1, wn = w & 1;
    const int b = blockIdx.z, j0 = blockIdx.y * 128, d0 = blockIdx.x * 64;

    const __half* dwb = g_dwh  + (size_t)b * SEQ * SEQ;   // [j][i]
    const __half* kvb = g_kwvh + (size_t)b * DIM * SEQ;   // [d][i]
    const __half* kwb = g_kwh  + (size_t)b * DIM * SEQ;   // [d][i]

    const __half* srcA  = dwb + (size_t)(j0 + t) * SEQ;
    const __half* srcB1 = kvb + (size_t)(d0 + (t >> 1)) * SEQ;
    const __half* srcB2 = kwb + (size_t)(d0 + (t >> 1)) * SEQ;

    float acc1[4][4][4] = {};
    float acc2[4][4][4] = {};

    // ldmatrix geometry
    const uint32_t aRow = wm * 64 + (l & 15);
    const uint32_t aCol = 8 * (l >> 4);
    const uint32_t bRow = wn * 32 + 8 * (l >> 4) + (l & 7);
    const uint32_t bCol = 8 * ((l >> 3) & 1);
    const uint32_t aOff  = (aRow * ASTH + aCol) * 2;
    const uint32_t b1Off = AA_BYTES + (bRow * ASTH + bCol) * 2;
    const uint32_t b2Off = b1Off + AB_BYTES;

    auto load_stage = [&](int tile, int stage) {
        const int i0 = tile * 32;
        const uint32_t s0 = sb + stage * ASTG_BYTES;
        const uint32_t aBase = s0 + t * (ASTH * 2);
        #pragma unroll
        for (int ch = 0; ch < 4; ch++)
            CP_ASYNC16(aBase + ch * 16, srcA + i0 + ch * 8);
        const int bch = 2 * (t & 1);
        const uint32_t b1Base = s0 + AA_BYTES + (t >> 1) * (ASTH * 2);
        const uint32_t b2Base = b1Base + AB_BYTES;
        CP_ASYNC16(b1Base + bch * 16,       srcB1 + i0 + bch * 8);
        CP_ASYNC16(b1Base + (bch + 1) * 16, srcB1 + i0 + (bch + 1) * 8);
        CP_ASYNC16(b2Base + bch * 16,       srcB2 + i0 + bch * 8);
        CP_ASYNC16(b2Base + (bch + 1) * 16, srcB2 + i0 + (bch + 1) * 8);
        CP_COMMIT();
    };

    auto compute_stage = [&](int stage) {
        const uint32_t s0 = sb + stage * ASTG_BYTES;
        #pragma unroll
        for (int ks = 0; ks < 2; ks++) {
            const int kk = ks * 16;
            uint32_t a[4][4], b1[4][2], b2[4][2];
            #pragma unroll
            for (int mt = 0; mt < 4; mt++)
                ldsm_x4(a[mt], s0 + aOff + (mt * 16 * ASTH + kk) * 2);
            #pragma unroll
            for (int np = 0; np < 2; np++) {
                uint32_t r[4];
                ldsm_x4(r, s0 + b1Off + (np * 16 * ASTH + kk) * 2);
                b1[np * 2][0] = r[0]; b1[np * 2][1] = r[1];
                b1[np * 2 + 1][0] = r[2]; b1[np * 2 + 1][1] = r[3];
                ldsm_x4(r, s0 + b2Off + (np * 16 * ASTH + kk) * 2);
                b2[np * 2][0] = r[0]; b2[np * 2][1] = r[1];
                b2[np * 2 + 1][0] = r[2]; b2[np * 2 + 1][1] = r[3];
            }
            #pragma unroll
            for (int mt = 0; mt < 4; mt++) {
                #pragma unroll
                for (int nt = 0; nt < 4; nt++) {
                    mma16(acc1[mt][nt], a[mt], b1[nt]);
                    mma16(acc2[mt][nt], a[mt], b2[nt]);
                }
            }
        }
    };

    load_stage(0, 0);
    load_stage(1, 1);
    for (int tile = 0; tile < N_ITILE; tile++) {
        if (tile == N_ITILE - 1) { CP_WAIT(0); } else { CP_WAIT(1); }
        __syncthreads();
        compute_stage(tile % 3);
        if (tile + 2 < N_ITILE) load_stage(tile + 2, (tile + 2) % 3);
    }

    // epilogue: out = sig * acc1/acc2
    const float* sigb = g_sig + (size_t)b * SEQ * DIM;
    float* outb = out + (size_t)b * SEQ * DIM;
    #pragma unroll
    for (int mt = 0; mt < 4; mt++) {
        #pragma unroll
        for (int nt = 0; nt < 4; nt++) {
            int jr = j0 + wm * 64 + mt * 16 + (l >> 2);
            int dc = d0 + wn * 32 + nt * 8 + 2 * (l & 3);
            size_t i0x = (size_t)jr * DIM + dc;
            size_t i1x = (size_t)(jr + 8) * DIM + dc;
            float2 s0 = *(const float2*)&sigb[i0x];
            float2 s1 = *(const float2*)&sigb[i1x];
            float2 o0, o1;
            o0.x = s0.x * __fdividef(acc1[mt][nt][0], acc2[mt][nt][0]);
            o0.y = s0.y * __fdividef(acc1[mt][nt][1], acc2[mt][nt][1]);
            o1.x = s1.x * __fdividef(acc1[mt][nt][2], acc2[mt][nt][2]);
            o1.y = s1.y * __fdividef(acc1[mt][nt][3], acc2[mt][nt][3]);
            *(float2*)&outb[i0x] = o0;
            *(float2*)&outb[i1x] = o1;
        }
    }
}

// ---------------------------------------------------------------------------
// Launch
// ---------------------------------------------------------------------------
extern "C" void kernel_launch(void* const* d_in, const int* in_sizes, int n_in,
                              void* d_out, int out_size) {
    const float* x     = (const float*)d_in[0];
    const float* dis   = (const float*)d_in[1];
    const float* Wq    = (const float*)d_in[2];
    const float* Wk    = (const float*)d_in[3];
    const float* Wv    = (const float*)d_in[4];
    const float* alpha = (const float*)d_in[5];
    float* out = (float*)d_out;

    cudaFuncSetAttribute(attn_kernel, cudaFuncAttributeMaxDynamicSharedMemorySize, ATTN_SMEM);
    cudaFuncSetAttribute(qkv_kernel,  cudaFuncAttributeMaxDynamicSharedMemorySize, QKV_SMEM);

    {   // weight convert+concat (fp16, [n][k])
        dim3 grid(256, 3), block(256);
        wconv_kernel<<<grid, block>>>(Wq, Wk, Wv);
    }
    {   // x convert
        xh_kernel<<<8192, 256>>>(x);
    }
    {   // dw = fp16(exp(coef*dis)) transposed [b][j][i]
        dim3 grid(SEQ / 32, SEQ / 32, BATCH), block(32, 8);
        dwt_kernel<<<grid, block>>>(dis, alpha);
    }
    {   // fp16 QKV projection
        dim3 grid(NCAT / 128, M_TOT / 128), block(128);
        qkv_kernel<<<grid, block, QKV_SMEM>>>();
    }
    {   // kw / kw*v transpose to fp16 [b][d][i]
        dim3 grid(DIM / 32, SEQ / 32, BATCH), block(32, 8);
        kvt_kernel<<<grid, block>>>();
    }
    {   // fp16 dual-GEMM attention
        dim3 grid(DIM / 64, SEQ / 128, BATCH), block(128);
        attn_kernel<<<grid, block, ATTN_SMEM>>>(out);
    }
}